// round 5
// baseline (speedup 1.0000x reference)
#include <cuda_runtime.h>

#define BATCH 4
#define HDIM 384
#define WDIM 384
#define NPIX (BATCH*HDIM*WDIM)

__device__ float g_q[NPIX*64];
__device__ float g_k[NPIX*64];
__device__ float g_v[NPIX*64];
// Pre-converted tf32 weights in smem-ready padded layouts
__device__ float g_wqkv[64*200];      // [k][200]: wq|wk|wv
__device__ float g_ff1h[2*64*72];     // half P: [k][72]
__device__ float g_ff2h[2*64*72];     // half Kp: [k][72]
__device__ float g_wfuse72[64*72];    // [k][72]

__device__ __forceinline__ float tf32r(float x) {
    unsigned u;
    asm("cvt.rna.tf32.f32 %0, %1;" : "=r"(u) : "f"(x));
    return __uint_as_float(u);
}

__device__ __forceinline__ void mma_tf32(float* d,
    unsigned a0, unsigned a1, unsigned a2, unsigned a3,
    unsigned b0, unsigned b1)
{
    asm volatile("mma.sync.aligned.m16n8k8.row.col.f32.tf32.tf32.f32 "
        "{%0,%1,%2,%3}, {%4,%5,%6,%7}, {%8,%9}, {%0,%1,%2,%3};"
        : "+f"(d[0]), "+f"(d[1]), "+f"(d[2]), "+f"(d[3])
        : "r"(a0), "r"(a1), "r"(a2), "r"(a3), "r"(b0), "r"(b1));
}

// ---------------------------------------------------------------------------
// One-time weight prep
// ---------------------------------------------------------------------------
__global__ void __launch_bounds__(256) cvt_weights_kernel(
    const float* __restrict__ wq, const float* __restrict__ wk,
    const float* __restrict__ wv, const float* __restrict__ ff1_w,
    const float* __restrict__ ff2_w, const float* __restrict__ w_fuse)
{
    int i = blockIdx.x*256 + threadIdx.x;
    if (i < 12800) {
        int k = i / 200, n = i % 200;
        float v = 0.f;
        if (n < 64)       v = tf32r(wq[k*64 + n]);
        else if (n < 128) v = tf32r(wk[k*64 + n - 64]);
        else if (n < 192) v = tf32r(wv[k*64 + n - 128]);
        g_wqkv[i] = v;
        return;
    }
    i -= 12800;
    if (i < 9216) {
        int P = i / 4608, r = i % 4608, k = r / 72, n = r % 72;
        g_ff1h[i] = (n < 64) ? tf32r(ff1_w[k*128 + P*64 + n]) : 0.f;
        return;
    }
    i -= 9216;
    if (i < 9216) {
        int Kp = i / 4608, r = i % 4608, k = r / 72, n = r % 72;
        g_ff2h[i] = (n < 64) ? tf32r(ff2_w[(Kp*64 + k)*64 + n]) : 0.f;
        return;
    }
    i -= 9216;
    if (i < 4608) {
        int k = i / 72, n = i % 72;
        g_wfuse72[i] = (n < 64) ? tf32r(w_fuse[k*64 + n]) : 0.f;
    }
}

// ---------------------------------------------------------------------------
// Kernel A: qkv projection. 128 pixels/block, 512 threads (16 warps).
// Warp tile 32m x 48n (2 m16-tiles x 6 j-tiles = 12 mma, 48 accum regs).
// ws [64][200], xs [128][68]
// ---------------------------------------------------------------------------
__global__ void __launch_bounds__(512,1) qkv_kernel(const float* __restrict__ x)
{
    extern __shared__ float sm[];
    float* ws = sm;            // [64][200]
    float* xs = sm + 12800;    // [128][68]
    const int tid = threadIdx.x;

    {
        const float4* src = (const float4*)g_wqkv;
        float4* dst = (float4*)ws;
        for (int i = tid; i < 3200; i += 512) dst[i] = src[i];
    }
    const int pix0 = blockIdx.x * 128;
    const float4* xg = (const float4*)(x + pix0*64);
    for (int i = tid; i < 2048; i += 512) {
        int m = i >> 4, c4 = i & 15;
        float4 v = xg[i];
        v.x = tf32r(v.x); v.y = tf32r(v.y); v.z = tf32r(v.z); v.w = tf32r(v.w);
        *(float4*)&xs[m*68 + c4*4] = v;
    }
    __syncthreads();

    const int wid = tid >> 5, lane = tid & 31;
    const int gr = lane >> 2, tg = lane & 3;
    const int m0 = (wid >> 2) * 32;
    const int n0 = (wid & 3) * 48;
    const unsigned* xs32 = (const unsigned*)xs;
    const unsigned* ws32 = (const unsigned*)ws;

    float d[12][4];
    #pragma unroll
    for (int j = 0; j < 12; j++)
        #pragma unroll
        for (int c = 0; c < 4; c++) d[j][c] = 0.f;

    #pragma unroll
    for (int k0 = 0; k0 < 64; k0 += 8) {
        unsigned a[2][4];
        #pragma unroll
        for (int t = 0; t < 2; t++) {
            int mr = m0 + 16*t + gr;
            a[t][0] = xs32[mr*68      + k0+tg];
            a[t][1] = xs32[(mr+8)*68  + k0+tg];
            a[t][2] = xs32[mr*68      + k0+tg+4];
            a[t][3] = xs32[(mr+8)*68  + k0+tg+4];
        }
        #pragma unroll
        for (int j = 0; j < 6; j++) {
            int nn = n0 + j*8;
            unsigned b0 = ws32[(k0+tg)*200   + nn+gr];
            unsigned b1 = ws32[(k0+tg+4)*200 + nn+gr];
            #pragma unroll
            for (int t = 0; t < 2; t++)
                mma_tf32(d[t*6+j], a[t][0], a[t][1], a[t][2], a[t][3], b0, b1);
        }
    }

    #pragma unroll
    for (int t = 0; t < 2; t++) {
        #pragma unroll
        for (int j = 0; j < 6; j++) {
            int n = n0 + j*8 + 2*tg;
            float* dst; int nn;
            if (n < 64)       { dst = g_q; nn = n; }
            else if (n < 128) { dst = g_k; nn = n - 64; }
            else              { dst = g_v; nn = n - 128; }
            int m = pix0 + m0 + 16*t + gr;
            *(float2*)&dst[m*64 + nn]     = make_float2(d[t*6+j][0], d[t*6+j][1]);
            *(float2*)&dst[(m+8)*64 + nn] = make_float2(d[t*6+j][2], d[t*6+j][3]);
        }
    }
}

// ---------------------------------------------------------------------------
// Kernel B: 2 image rows (128 pixels) per block, 256 threads (8 warps).
// Attention: thread = (x, head), handles BOTH rows; 3x4 halo loads shared.
// GEMMs: warp tile 32m x 32n.
// smem (floats):
//   region1 [0,21504): halo [264][68]=17952  |  s_w[64][72]=4608 + s_h[128][132]=16896
//   region2 [21504,30208): s_o [128][68]=8704
//   s_m     [30208,30784)
// ---------------------------------------------------------------------------
#define R2OFF 21504
#define MOFF  30208
#define SMB_FLOATS 30784

__global__ void __launch_bounds__(256,1) attn_ffn_kernel(
    const float* __restrict__ x,
    const float* __restrict__ ln1_g, const float* __restrict__ ln1_b,
    const float* __restrict__ ff1_b,
    const float* __restrict__ ff2_b,
    const float* __restrict__ ln2_g, const float* __restrict__ ln2_b,
    const float* __restrict__ bn_g, const float* __restrict__ bn_b,
    const float* __restrict__ bn_mean, const float* __restrict__ bn_var,
    float* __restrict__ out)
{
    extern __shared__ float sm[];
    float* s_halo = sm;               // [264][68]
    float* s_w    = sm;               // [64][72]
    float* s_h    = sm + 4608;        // [128][132]
    float* s_o    = sm + R2OFF;       // [128][68]
    float* s_m    = sm + MOFF;

    const int tid = threadIdx.x;
    if (tid < 64) {
        s_m[tid]        = ln1_g[tid];
        s_m[64 + tid]   = ln1_b[tid];
        s_m[128 + tid]  = ln2_g[tid];
        s_m[192 + tid]  = ln2_b[tid];
        s_m[384 + tid]  = ff2_b[tid];
        float sc = bn_g[tid] * rsqrtf(bn_var[tid] + 1e-3f);
        s_m[448 + tid]  = sc;
        s_m[512 + tid]  = bn_b[tid] - bn_mean[tid]*sc;
    } else if (tid < 192) {
        s_m[256 + (tid - 64)] = ff1_b[tid - 64];
    }

    const int b  = blockIdx.z;
    const int y0 = blockIdx.y * 2;
    const int c0 = blockIdx.x * 64;

    // ---- stage k halo: rows y0-1 .. y0+2 ----
    #pragma unroll
    for (int r = 0; r < 4; r++) {
        const int gy = y0 + r - 1;
        const bool rowok = (unsigned)gy < HDIM;
        const float* src = g_k + (((long)b*HDIM + gy)*WDIM + c0 - 1)*64;
        for (int idx = tid; idx < 1056; idx += 256) {
            int j = idx >> 4, c4 = idx & 15;
            int gx = c0 + j - 1;
            float4 v = make_float4(0.f, 0.f, 0.f, 0.f);
            if (rowok && (unsigned)gx < WDIM)
                v = *(const float4*)(src + j*64 + c4*4);
            *(float4*)&s_halo[(r*66 + j)*68 + c4*4] = v;
        }
    }

    const int p  = tid >> 2;
    const int hd = tid & 3;
    const int base0 = ((b*HDIM + y0)*WDIM + c0 + p)*64;
    const int base1 = base0 + WDIM*64;

    float q0[16], q1[16];
    #pragma unroll
    for (int i = 0; i < 4; i++) {
        *(float4*)&q0[4*i] = *(const float4*)(g_q + base0 + hd*16 + 4*i);
        *(float4*)&q1[4*i] = *(const float4*)(g_q + base1 + hd*16 + 4*i);
    }
    __syncthreads();

    // ---- scores for both rows; each halo vector loaded once ----
    float s0[9], s1[9];
    #pragma unroll
    for (int r = 0; r < 4; r++) {
        #pragma unroll
        for (int dx = 0; dx < 3; dx++) {
            const float* kp = &s_halo[(r*66 + p + dx)*68 + hd*16];
            float kk[16];
            #pragma unroll
            for (int i = 0; i < 4; i++) *(float4*)&kk[4*i] = *(const float4*)&kp[4*i];
            if (r < 3) {
                float s = 0.f;
                #pragma unroll
                for (int dd = 0; dd < 16; dd++) s = fmaf(q0[dd], kk[dd], s);
                s0[r*3 + dx] = s * 0.25f;
            }
            if (r > 0) {
                float s = 0.f;
                #pragma unroll
                for (int dd = 0; dd < 16; dd++) s = fmaf(q1[dd], kk[dd], s);
                s1[(r-1)*3 + dx] = s * 0.25f;
            }
        }
    }
    // softmax per pixel
    float mx0 = s0[0], mx1 = s1[0];
    #pragma unroll
    for (int o = 1; o < 9; o++) { mx0 = fmaxf(mx0, s0[o]); mx1 = fmaxf(mx1, s1[o]); }
    float sum0 = 0.f, sum1 = 0.f;
    #pragma unroll
    for (int o = 0; o < 9; o++) {
        s0[o] = __expf(s0[o] - mx0); sum0 += s0[o];
        s1[o] = __expf(s1[o] - mx1); sum1 += s1[o];
    }
    const float si0 = 1.f/sum0, si1 = 1.f/sum1;
    #pragma unroll
    for (int o = 0; o < 9; o++) { s0[o] *= si0; s1[o] *= si1; }

    float xr0[16], xr1[16];
    #pragma unroll
    for (int i = 0; i < 4; i++) {
        *(float4*)&xr0[4*i] = *(const float4*)(x + base0 + hd*16 + 4*i);
        *(float4*)&xr1[4*i] = *(const float4*)(x + base1 + hd*16 + 4*i);
    }

    __syncthreads();
    // ---- stage v halo ----
    #pragma unroll
    for (int r = 0; r < 4; r++) {
        const int gy = y0 + r - 1;
        const bool rowok = (unsigned)gy < HDIM;
        const float* src = g_v + (((long)b*HDIM + gy)*WDIM + c0 - 1)*64;
        for (int idx = tid; idx < 1056; idx += 256) {
            int j = idx >> 4, c4 = idx & 15;
            int gx = c0 + j - 1;
            float4 v = make_float4(0.f, 0.f, 0.f, 0.f);
            if (rowok && (unsigned)gx < WDIM)
                v = *(const float4*)(src + j*64 + c4*4);
            *(float4*)&s_halo[(r*66 + j)*68 + c4*4] = v;
        }
    }
    __syncthreads();

    // ---- weighted v sums for both rows ----
    float a0[16], a1[16];
    #pragma unroll
    for (int dd = 0; dd < 16; dd++) { a0[dd] = 0.f; a1[dd] = 0.f; }
    #pragma unroll
    for (int r = 0; r < 4; r++) {
        #pragma unroll
        for (int dx = 0; dx < 3; dx++) {
            const float* vp = &s_halo[(r*66 + p + dx)*68 + hd*16];
            float vv[16];
            #pragma unroll
            for (int i = 0; i < 4; i++) *(float4*)&vv[4*i] = *(const float4*)&vp[4*i];
            if (r < 3) {
                const float w = s0[r*3 + dx];
                #pragma unroll
                for (int dd = 0; dd < 16; dd++) a0[dd] = fmaf(w, vv[dd], a0[dd]);
            }
            if (r > 0) {
                const float w = s1[(r-1)*3 + dx];
                #pragma unroll
                for (int dd = 0; dd < 16; dd++) a1[dd] = fmaf(w, vv[dd], a1[dd]);
            }
        }
    }

    // ---- LN1 (+residual) for both pixels; write tf32 to s_o rows p, 64+p ----
    #pragma unroll
    for (int rr = 0; rr < 2; rr++) {
        float* av = rr ? a1 : a0;
        float* xv = rr ? xr1 : xr0;
        float m1 = 0.f, m2 = 0.f;
        #pragma unroll
        for (int dd = 0; dd < 16; dd++) {
            av[dd] += xv[dd];
            m1 += av[dd];
            m2 = fmaf(av[dd], av[dd], m2);
        }
        m1 += __shfl_xor_sync(0xffffffff, m1, 1);
        m2 += __shfl_xor_sync(0xffffffff, m2, 1);
        m1 += __shfl_xor_sync(0xffffffff, m1, 2);
        m2 += __shfl_xor_sync(0xffffffff, m2, 2);
        const float mean = m1 * (1.f/64.f);
        const float var  = m2 * (1.f/64.f) - mean*mean;
        const float rstd = rsqrtf(var + 1e-3f);
        float* dst = &s_o[(rr*64 + p)*68];
        #pragma unroll
        for (int i = 0; i < 4; i++) {
            const int c = hd*16 + 4*i;
            float4 w4;
            w4.x = tf32r((av[4*i+0] - mean)*rstd*s_m[c+0] + s_m[64+c+0]);
            w4.y = tf32r((av[4*i+1] - mean)*rstd*s_m[c+1] + s_m[64+c+1]);
            w4.z = tf32r((av[4*i+2] - mean)*rstd*s_m[c+2] + s_m[64+c+2]);
            w4.w = tf32r((av[4*i+3] - mean)*rstd*s_m[c+3] + s_m[64+c+3]);
            *(float4*)&dst[c] = w4;
        }
    }
    __syncthreads();   // halo dead; LN1 visible

    const int wid = tid >> 5, lane = tid & 31;
    const int gr = lane >> 2, tg = lane & 3;
    const int m0 = (wid >> 1) * 32;
    const int wn = wid & 1;
    const unsigned* so32 = (const unsigned*)s_o;
    const unsigned* sh32 = (const unsigned*)s_h;
    const unsigned* sw32 = (const unsigned*)s_w;

    // ---- GEMM1: h = relu(o @ ff1 + b1), two n-halves, M=128 ----
    #pragma unroll
    for (int P = 0; P < 2; P++) {
        {
            const float4* src = (const float4*)(g_ff1h + P*4608);
            float4* dst = (float4*)s_w;
            for (int i = tid; i < 1152; i += 256) dst[i] = src[i];
        }
        __syncthreads();
        float d1[8][4];
        #pragma unroll
        for (int j = 0; j < 8; j++)
            #pragma unroll
            for (int c = 0; c < 4; c++) d1[j][c] = 0.f;
        #pragma unroll
        for (int k0 = 0; k0 < 64; k0 += 8) {
            unsigned a[2][4];
            #pragma unroll
            for (int t = 0; t < 2; t++) {
                int mr = m0 + 16*t + gr;
                a[t][0] = so32[mr*68     + k0+tg];
                a[t][1] = so32[(mr+8)*68 + k0+tg];
                a[t][2] = so32[mr*68     + k0+tg+4];
                a[t][3] = so32[(mr+8)*68 + k0+tg+4];
            }
            #pragma unroll
            for (int j = 0; j < 4; j++) {
                int nn = wn*32 + j*8;
                unsigned b0 = sw32[(k0+tg)*72   + nn+gr];
                unsigned b1 = sw32[(k0+tg+4)*72 + nn+gr];
                #pragma unroll
                for (int t = 0; t < 2; t++)
                    mma_tf32(d1[t*4+j], a[t][0], a[t][1], a[t][2], a[t][3], b0, b1);
            }
        }
        #pragma unroll
        for (int t = 0; t < 2; t++) {
            #pragma unroll
            for (int j = 0; j < 4; j++) {
                int n = P*64 + wn*32 + j*8 + 2*tg;
                int mr = m0 + 16*t + gr;
                float bb0 = s_m[256 + n], bb1 = s_m[256 + n + 1];
                *(float2*)&s_h[mr*132 + n] = make_float2(
                    tf32r(fmaxf(d1[t*4+j][0] + bb0, 0.f)), tf32r(fmaxf(d1[t*4+j][1] + bb1, 0.f)));
                *(float2*)&s_h[(mr+8)*132 + n] = make_float2(
                    tf32r(fmaxf(d1[t*4+j][2] + bb0, 0.f)), tf32r(fmaxf(d1[t*4+j][3] + bb1, 0.f)));
            }
        }
        __syncthreads();
    }

    // ---- GEMM2: o += h @ ff2 + b2, two k-halves ----
    float d2[8][4];
    #pragma unroll
    for (int j = 0; j < 8; j++)
        #pragma unroll
        for (int c = 0; c < 4; c++) d2[j][c] = 0.f;
    #pragma unroll
    for (int Kp = 0; Kp < 2; Kp++) {
        {
            const float4* src = (const float4*)(g_ff2h + Kp*4608);
            float4* dst = (float4*)s_w;
            for (int i = tid; i < 1152; i += 256) dst[i] = src[i];
        }
        __syncthreads();
        #pragma unroll
        for (int k0 = 0; k0 < 64; k0 += 8) {
            int kc = Kp*64 + k0;
            unsigned a[2][4];
            #pragma unroll
            for (int t = 0; t < 2; t++) {
                int mr = m0 + 16*t + gr;
                a[t][0] = sh32[mr*132     + kc+tg];
                a[t][1] = sh32[(mr+8)*132 + kc+tg];
                a[t][2] = sh32[mr*132     + kc+tg+4];
                a[t][3] = sh32[(mr+8)*132 + kc+tg+4];
            }
            #pragma unroll
            for (int j = 0; j < 4; j++) {
                int nn = wn*32 + j*8;
                unsigned b0 = sw32[(k0+tg)*72   + nn+gr];
                unsigned b1 = sw32[(k0+tg+4)*72 + nn+gr];
                #pragma unroll
                for (int t = 0; t < 2; t++)
                    mma_tf32(d2[t*4+j], a[t][0], a[t][1], a[t][2], a[t][3], b0, b1);
            }
        }
        __syncthreads();
    }
    #pragma unroll
    for (int t = 0; t < 2; t++) {
        #pragma unroll
        for (int j = 0; j < 4; j++) {
            int n = wn*32 + j*8 + 2*tg;
            int mr = m0 + 16*t + gr;
            float bb0 = s_m[384 + n], bb1 = s_m[384 + n + 1];
            float2 o0 = *(float2*)&s_o[mr*68 + n];
            float2 o1 = *(float2*)&s_o[(mr+8)*68 + n];
            *(float2*)&s_o[mr*68 + n]     = make_float2(o0.x + d2[t*4+j][0] + bb0, o0.y + d2[t*4+j][1] + bb1);
            *(float2*)&s_o[(mr+8)*68 + n] = make_float2(o1.x + d2[t*4+j][2] + bb0, o1.y + d2[t*4+j][3] + bb1);
        }
    }
    __syncthreads();

    // ---- LN2 for both pixels; write tf32 ----
    #pragma unroll
    for (int rr = 0; rr < 2; rr++) {
        float* row = &s_o[(rr*64 + p)*68];
        float v2[16], m1 = 0.f, m2 = 0.f;
        #pragma unroll
        for (int i = 0; i < 4; i++) {
            float4 t4 = *(const float4*)&row[hd*16 + 4*i];
            v2[4*i+0] = t4.x; v2[4*i+1] = t4.y; v2[4*i+2] = t4.z; v2[4*i+3] = t4.w;
        }
        #pragma unroll
        for (int dd = 0; dd < 16; dd++) { m1 += v2[dd]; m2 = fmaf(v2[dd], v2[dd], m2); }
        m1 += __shfl_xor_sync(0xffffffff, m1, 1);
        m2 += __shfl_xor_sync(0xffffffff, m2, 1);
        m1 += __shfl_xor_sync(0xffffffff, m1, 2);
        m2 += __shfl_xor_sync(0xffffffff, m2, 2);
        const float mean = m1 * (1.f/64.f);
        const float var  = m2 * (1.f/64.f) - mean*mean;
        const float rstd = rsqrtf(var + 1e-3f);
        #pragma unroll
        for (int i = 0; i < 4; i++) {
            const int c = hd*16 + 4*i;
            float4 w4;
            w4.x = tf32r((v2[4*i+0] - mean)*rstd*s_m[128+c+0] + s_m[192+c+0]);
            w4.y = tf32r((v2[4*i+1] - mean)*rstd*s_m[128+c+1] + s_m[192+c+1]);
            w4.z = tf32r((v2[4*i+2] - mean)*rstd*s_m[128+c+2] + s_m[192+c+2]);
            w4.w = tf32r((v2[4*i+3] - mean)*rstd*s_m[128+c+3] + s_m[192+c+3]);
            *(float4*)&row[c] = w4;
        }
    }
    // stage fuse weights (s_w free since GEMM2 sync)
    {
        const float4* src = (const float4*)g_wfuse72;
        float4* dst = (float4*)s_w;
        for (int i = tid; i < 1152; i += 256) dst[i] = src[i];
    }
    __syncthreads();

    // ---- GEMM3: fuse conv + BN + relu, direct global store ----
    {
        float d3[8][4];
        #pragma unroll
        for (int j = 0; j < 8; j++)
            #pragma unroll
            for (int c = 0; c < 4; c++) d3[j][c] = 0.f;
        #pragma unroll
        for (int k0 = 0; k0 < 64; k0 += 8) {
            unsigned a[2][4];
            #pragma unroll
            for (int t = 0; t < 2; t++) {
                int mr = m0 + 16*t + gr;
                a[t][0] = so32[mr*68     + k0+tg];
                a[t][1] = so32[(mr+8)*68 + k0+tg];
                a[t][2] = so32[mr*68     + k0+tg+4];
                a[t][3] = so32[(mr+8)*68 + k0+tg+4];
            }
            #pragma unroll
            for (int j = 0; j < 4; j++) {
                int nn = wn*32 + j*8;
                unsigned b0 = sw32[(k0+tg)*72   + nn+gr];
                unsigned b1 = sw32[(k0+tg+4)*72 + nn+gr];
                #pragma unroll
                for (int t = 0; t < 2; t++)
                    mma_tf32(d3[t*4+j], a[t][0], a[t][1], a[t][2], a[t][3], b0, b1);
            }
        }
        #pragma unroll
        for (int t = 0; t < 2; t++) {
            #pragma unroll
            for (int j = 0; j < 4; j++) {
                int n = wn*32 + j*8 + 2*tg;
                int mr = m0 + 16*t + gr;       // 0..127
                int ry = mr >> 6, mx = mr & 63;
                float sc0 = s_m[448 + n], sc1 = s_m[448 + n + 1];
                float sh0 = s_m[512 + n], sh1 = s_m[512 + n + 1];
                float* ob0 = out + ((b*HDIM + y0 + ry)*WDIM + c0 + mx)*64;
                // mr+8 stays within the same 64-row half (m0+16t+gr+8 <= m0+31)
                float* ob1 = out + ((b*HDIM + y0 + ry)*WDIM + c0 + mx + 8)*64;
                *(float2*)&ob0[n] = make_float2(
                    fmaxf(d3[t*4+j][0]*sc0 + sh0, 0.f), fmaxf(d3[t*4+j][1]*sc1 + sh1, 0.f));
                *(float2*)&ob1[n] = make_float2(
                    fmaxf(d3[t*4+j][2]*sc0 + sh0, 0.f), fmaxf(d3[t*4+j][3]*sc1 + sh1, 0.f));
            }
        }
    }
}

extern "C" void kernel_launch(void* const* d_in, const int* in_sizes, int n_in,
                              void* d_out, int out_size)
{
    const float* x      = (const float*)d_in[0];
    const float* wq     = (const float*)d_in[1];
    const float* wk     = (const float*)d_in[2];
    const float* wv     = (const float*)d_in[3];
    const float* ln1_g  = (const float*)d_in[4];
    const float* ln1_b  = (const float*)d_in[5];
    const float* ff1_w  = (const float*)d_in[6];
    const float* ff1_b  = (const float*)d_in[7];
    const float* ff2_w  = (const float*)d_in[8];
    const float* ff2_b  = (const float*)d_in[9];
    const float* ln2_g  = (const float*)d_in[10];
    const float* ln2_b  = (const float*)d_in[11];
    const float* w_fuse = (const float*)d_in[12];
    const float* bn_g   = (const float*)d_in[13];
    const float* bn_b   = (const float*)d_in[14];
    const float* bn_mean= (const float*)d_in[15];
    const float* bn_var = (const float*)d_in[16];
    float* out = (float*)d_out;

    const int SMEM_A = (12800 + 128*68) * 4;  // 86016 B
    const int SMEM_B = SMB_FLOATS * 4;        // 123136 B
    cudaFuncSetAttribute(qkv_kernel, cudaFuncAttributeMaxDynamicSharedMemorySize, SMEM_A);
    cudaFuncSetAttribute(attn_ffn_kernel, cudaFuncAttributeMaxDynamicSharedMemorySize, SMEM_B);

    cvt_weights_kernel<<<140, 256>>>(wq, wk, wv, ff1_w, ff2_w, w_fuse);
    qkv_kernel<<<NPIX/128, 512, SMEM_A>>>(x);

    dim3 grid(WDIM/64, HDIM/2, BATCH);
    attn_ffn_kernel<<<grid, 256, SMEM_B>>>(
        x, ln1_g, ln1_b, ff1_b, ff2_b,
        ln2_g, ln2_b, bn_g, bn_b, bn_mean, bn_var, out);
}

// round 6
// speedup vs baseline: 1.4373x; 1.4373x over previous
#include <cuda_runtime.h>

#define BATCH 4
#define HDIM 384
#define WDIM 384
#define NPIX (BATCH*HDIM*WDIM)

__device__ float g_q[NPIX*64];
__device__ float g_k[NPIX*64];
__device__ float g_v[NPIX*64];
// Pre-converted tf32 weights in smem-ready padded layouts
__device__ float g_wqkv[64*200];      // [k][200]: wq|wk|wv
__device__ float g_ff1h[2*64*72];     // half P: [k][72]
__device__ float g_ff2h[2*64*72];     // half Kp: [k][72]
__device__ float g_wfuse72[64*72];    // [k][72]

__device__ __forceinline__ float tf32r(float x) {
    unsigned u;
    asm("cvt.rna.tf32.f32 %0, %1;" : "=r"(u) : "f"(x));
    return __uint_as_float(u);
}

__device__ __forceinline__ void mma_tf32(float* d,
    unsigned a0, unsigned a1, unsigned a2, unsigned a3,
    unsigned b0, unsigned b1)
{
    asm volatile("mma.sync.aligned.m16n8k8.row.col.f32.tf32.tf32.f32 "
        "{%0,%1,%2,%3}, {%4,%5,%6,%7}, {%8,%9}, {%0,%1,%2,%3};"
        : "+f"(d[0]), "+f"(d[1]), "+f"(d[2]), "+f"(d[3])
        : "r"(a0), "r"(a1), "r"(a2), "r"(a3), "r"(b0), "r"(b1));
}

// ---------------------------------------------------------------------------
// One-time weight prep
// ---------------------------------------------------------------------------
__global__ void __launch_bounds__(256) cvt_weights_kernel(
    const float* __restrict__ wq, const float* __restrict__ wk,
    const float* __restrict__ wv, const float* __restrict__ ff1_w,
    const float* __restrict__ ff2_w, const float* __restrict__ w_fuse)
{
    int i = blockIdx.x*256 + threadIdx.x;
    if (i < 12800) {
        int k = i / 200, n = i % 200;
        float v = 0.f;
        if (n < 64)       v = tf32r(wq[k*64 + n]);
        else if (n < 128) v = tf32r(wk[k*64 + n - 64]);
        else if (n < 192) v = tf32r(wv[k*64 + n - 128]);
        g_wqkv[i] = v;
        return;
    }
    i -= 12800;
    if (i < 9216) {
        int P = i / 4608, r = i % 4608, k = r / 72, n = r % 72;
        g_ff1h[i] = (n < 64) ? tf32r(ff1_w[k*128 + P*64 + n]) : 0.f;
        return;
    }
    i -= 9216;
    if (i < 9216) {
        int Kp = i / 4608, r = i % 4608, k = r / 72, n = r % 72;
        g_ff2h[i] = (n < 64) ? tf32r(ff2_w[(Kp*64 + k)*64 + n]) : 0.f;
        return;
    }
    i -= 9216;
    if (i < 4608) {
        int k = i / 72, n = i % 72;
        g_wfuse72[i] = (n < 64) ? tf32r(w_fuse[k*64 + n]) : 0.f;
    }
}

// ---------------------------------------------------------------------------
// Kernel A: qkv projection (r4 version). 64 pixels/block, 256 threads.
// ---------------------------------------------------------------------------
__global__ void __launch_bounds__(256,2) qkv_kernel(const float* __restrict__ x)
{
    extern __shared__ float sm[];
    float* ws = sm;            // [64][200]
    float* xs = sm + 12800;    // [64][68]
    const int tid = threadIdx.x;

    {
        const float4* src = (const float4*)g_wqkv;
        float4* dst = (float4*)ws;
        for (int i = tid; i < 3200; i += 256) dst[i] = src[i];
    }
    const int pix0 = blockIdx.x * 64;
    const float4* xg = (const float4*)(x + pix0*64);
    for (int i = tid; i < 1024; i += 256) {
        int m = i >> 4, c4 = i & 15;
        float4 v = xg[i];
        v.x = tf32r(v.x); v.y = tf32r(v.y); v.z = tf32r(v.z); v.w = tf32r(v.w);
        *(float4*)&xs[m*68 + c4*4] = v;
    }
    __syncthreads();

    const int wid = tid >> 5, lane = tid & 31;
    const int gr = lane >> 2, tg = lane & 3;
    const int m0 = (wid >> 1) * 16;
    const int nb = (wid & 1) * 96;
    const unsigned* xs32 = (const unsigned*)xs;
    const unsigned* ws32 = (const unsigned*)ws;

    float d[12][4];
    #pragma unroll
    for (int j = 0; j < 12; j++)
        #pragma unroll
        for (int c = 0; c < 4; c++) d[j][c] = 0.f;

    #pragma unroll
    for (int k0 = 0; k0 < 64; k0 += 8) {
        unsigned a0 = xs32[(m0+gr)*68   + k0+tg];
        unsigned a1 = xs32[(m0+gr+8)*68 + k0+tg];
        unsigned a2 = xs32[(m0+gr)*68   + k0+tg+4];
        unsigned a3 = xs32[(m0+gr+8)*68 + k0+tg+4];
        #pragma unroll
        for (int j = 0; j < 12; j++) {
            int n0 = nb + j*8;
            unsigned b0 = ws32[(k0+tg)*200   + n0+gr];
            unsigned b1 = ws32[(k0+tg+4)*200 + n0+gr];
            mma_tf32(d[j], a0, a1, a2, a3, b0, b1);
        }
    }

    #pragma unroll
    for (int j = 0; j < 12; j++) {
        int n = nb + j*8 + 2*tg;
        float* dst; int nn;
        if (n < 64)       { dst = g_q; nn = n; }
        else if (n < 128) { dst = g_k; nn = n - 64; }
        else              { dst = g_v; nn = n - 128; }
        int m = pix0 + m0 + gr;
        *(float2*)&dst[m*64 + nn]     = make_float2(d[j][0], d[j][1]);
        *(float2*)&dst[(m+8)*64 + nn] = make_float2(d[j][2], d[j][3]);
    }
}

// ---------------------------------------------------------------------------
// Kernel B: 2 image rows (128 pixels)/block, 256 threads, 2 blocks/SM.
// FFN restructured: per-half fused GEMM1->GEMM2 with small s_h [128][68].
// smem (floats):
//   region1 [0,17952): halo [264][68]  |  s_w[64][72]=4608 + s_h[128][68]=8704
//   region2 [17952,26656): s_o [128][68]=8704
//   s_m     [26656,27232)
// ---------------------------------------------------------------------------
#define R2OFF 17952
#define MOFF  26656
#define SMB_FLOATS 27232

__global__ void __launch_bounds__(256,2) attn_ffn_kernel(
    const float* __restrict__ x,
    const float* __restrict__ ln1_g, const float* __restrict__ ln1_b,
    const float* __restrict__ ff1_b,
    const float* __restrict__ ff2_b,
    const float* __restrict__ ln2_g, const float* __restrict__ ln2_b,
    const float* __restrict__ bn_g, const float* __restrict__ bn_b,
    const float* __restrict__ bn_mean, const float* __restrict__ bn_var,
    float* __restrict__ out)
{
    extern __shared__ float sm[];
    float* s_halo = sm;               // [264][68]
    float* s_w    = sm;               // [64][72] (aliases halo)
    float* s_h    = sm + 4608;        // [128][68]
    float* s_o    = sm + R2OFF;       // [128][68]
    float* s_m    = sm + MOFF;

    const int tid = threadIdx.x;
    if (tid < 64) {
        s_m[tid]        = ln1_g[tid];
        s_m[64 + tid]   = ln1_b[tid];
        s_m[128 + tid]  = ln2_g[tid];
        s_m[192 + tid]  = ln2_b[tid];
        s_m[384 + tid]  = ff2_b[tid];
        float sc = bn_g[tid] * rsqrtf(bn_var[tid] + 1e-3f);
        s_m[448 + tid]  = sc;
        s_m[512 + tid]  = bn_b[tid] - bn_mean[tid]*sc;
    } else if (tid < 192) {
        s_m[256 + (tid - 64)] = ff1_b[tid - 64];
    }

    const int b  = blockIdx.z;
    const int y0 = blockIdx.y * 2;
    const int c0 = blockIdx.x * 64;

    // ---- stage k halo: rows y0-1 .. y0+2 ----
    #pragma unroll
    for (int r = 0; r < 4; r++) {
        const int gy = y0 + r - 1;
        const bool rowok = (unsigned)gy < HDIM;
        const float* src = g_k + (((long)b*HDIM + gy)*WDIM + c0 - 1)*64;
        for (int idx = tid; idx < 1056; idx += 256) {
            int j = idx >> 4, c4 = idx & 15;
            int gx = c0 + j - 1;
            float4 v = make_float4(0.f, 0.f, 0.f, 0.f);
            if (rowok && (unsigned)gx < WDIM)
                v = *(const float4*)(src + j*64 + c4*4);
            *(float4*)&s_halo[(r*66 + j)*68 + c4*4] = v;
        }
    }

    const int p  = tid >> 2;
    const int hd = tid & 3;
    const int base0 = ((b*HDIM + y0)*WDIM + c0 + p)*64;
    const int base1 = base0 + WDIM*64;

    float q0[16], q1[16];
    #pragma unroll
    for (int i = 0; i < 4; i++) {
        *(float4*)&q0[4*i] = *(const float4*)(g_q + base0 + hd*16 + 4*i);
        *(float4*)&q1[4*i] = *(const float4*)(g_q + base1 + hd*16 + 4*i);
    }
    __syncthreads();

    // ---- scores for both rows; each halo vector loaded once ----
    float s0[9], s1[9];
    #pragma unroll
    for (int r = 0; r < 4; r++) {
        #pragma unroll
        for (int dx = 0; dx < 3; dx++) {
            const float* kp = &s_halo[(r*66 + p + dx)*68 + hd*16];
            float kk[16];
            #pragma unroll
            for (int i = 0; i < 4; i++) *(float4*)&kk[4*i] = *(const float4*)&kp[4*i];
            if (r < 3) {
                float s = 0.f;
                #pragma unroll
                for (int dd = 0; dd < 16; dd++) s = fmaf(q0[dd], kk[dd], s);
                s0[r*3 + dx] = s * 0.25f;
            }
            if (r > 0) {
                float s = 0.f;
                #pragma unroll
                for (int dd = 0; dd < 16; dd++) s = fmaf(q1[dd], kk[dd], s);
                s1[(r-1)*3 + dx] = s * 0.25f;
            }
        }
    }
    float mx0 = s0[0], mx1 = s1[0];
    #pragma unroll
    for (int o = 1; o < 9; o++) { mx0 = fmaxf(mx0, s0[o]); mx1 = fmaxf(mx1, s1[o]); }
    float sum0 = 0.f, sum1 = 0.f;
    #pragma unroll
    for (int o = 0; o < 9; o++) {
        s0[o] = __expf(s0[o] - mx0); sum0 += s0[o];
        s1[o] = __expf(s1[o] - mx1); sum1 += s1[o];
    }
    const float si0 = 1.f/sum0, si1 = 1.f/sum1;
    #pragma unroll
    for (int o = 0; o < 9; o++) { s0[o] *= si0; s1[o] *= si1; }

    float xr0[16], xr1[16];
    #pragma unroll
    for (int i = 0; i < 4; i++) {
        *(float4*)&xr0[4*i] = *(const float4*)(x + base0 + hd*16 + 4*i);
        *(float4*)&xr1[4*i] = *(const float4*)(x + base1 + hd*16 + 4*i);
    }

    __syncthreads();
    // ---- stage v halo ----
    #pragma unroll
    for (int r = 0; r < 4; r++) {
        const int gy = y0 + r - 1;
        const bool rowok = (unsigned)gy < HDIM;
        const float* src = g_v + (((long)b*HDIM + gy)*WDIM + c0 - 1)*64;
        for (int idx = tid; idx < 1056; idx += 256) {
            int j = idx >> 4, c4 = idx & 15;
            int gx = c0 + j - 1;
            float4 v = make_float4(0.f, 0.f, 0.f, 0.f);
            if (rowok && (unsigned)gx < WDIM)
                v = *(const float4*)(src + j*64 + c4*4);
            *(float4*)&s_halo[(r*66 + j)*68 + c4*4] = v;
        }
    }
    __syncthreads();

    // ---- weighted v sums for both rows ----
    float a0[16], a1[16];
    #pragma unroll
    for (int dd = 0; dd < 16; dd++) { a0[dd] = 0.f; a1[dd] = 0.f; }
    #pragma unroll
    for (int r = 0; r < 4; r++) {
        #pragma unroll
        for (int dx = 0; dx < 3; dx++) {
            const float* vp = &s_halo[(r*66 + p + dx)*68 + hd*16];
            float vv[16];
            #pragma unroll
            for (int i = 0; i < 4; i++) *(float4*)&vv[4*i] = *(const float4*)&vp[4*i];
            if (r < 3) {
                const float w = s0[r*3 + dx];
                #pragma unroll
                for (int dd = 0; dd < 16; dd++) a0[dd] = fmaf(w, vv[dd], a0[dd]);
            }
            if (r > 0) {
                const float w = s1[(r-1)*3 + dx];
                #pragma unroll
                for (int dd = 0; dd < 16; dd++) a1[dd] = fmaf(w, vv[dd], a1[dd]);
            }
        }
    }

    // ---- LN1 (+residual) for both pixels; tf32 into s_o rows p, 64+p ----
    #pragma unroll
    for (int rr = 0; rr < 2; rr++) {
        float* av = rr ? a1 : a0;
        float* xv = rr ? xr1 : xr0;
        float m1 = 0.f, m2 = 0.f;
        #pragma unroll
        for (int dd = 0; dd < 16; dd++) {
            av[dd] += xv[dd];
            m1 += av[dd];
            m2 = fmaf(av[dd], av[dd], m2);
        }
        m1 += __shfl_xor_sync(0xffffffff, m1, 1);
        m2 += __shfl_xor_sync(0xffffffff, m2, 1);
        m1 += __shfl_xor_sync(0xffffffff, m1, 2);
        m2 += __shfl_xor_sync(0xffffffff, m2, 2);
        const float mean = m1 * (1.f/64.f);
        const float var  = m2 * (1.f/64.f) - mean*mean;
        const float rstd = rsqrtf(var + 1e-3f);
        float* dst = &s_o[(rr*64 + p)*68];
        #pragma unroll
        for (int i = 0; i < 4; i++) {
            const int c = hd*16 + 4*i;
            float4 w4;
            w4.x = tf32r((av[4*i+0] - mean)*rstd*s_m[c+0] + s_m[64+c+0]);
            w4.y = tf32r((av[4*i+1] - mean)*rstd*s_m[c+1] + s_m[64+c+1]);
            w4.z = tf32r((av[4*i+2] - mean)*rstd*s_m[c+2] + s_m[64+c+2]);
            w4.w = tf32r((av[4*i+3] - mean)*rstd*s_m[c+3] + s_m[64+c+3]);
            *(float4*)&dst[c] = w4;
        }
    }
    __syncthreads();   // halo dead; LN1 visible

    const int wid = tid >> 5, lane = tid & 31;
    const int gr = lane >> 2, tg = lane & 3;
    const int m0 = (wid >> 1) * 32;
    const int wn = wid & 1;
    const unsigned* so32 = (const unsigned*)s_o;
    const unsigned* sh32 = (const unsigned*)s_h;
    const unsigned* sw32 = (const unsigned*)s_w;

    // ---- fused FFN: per half P: GEMM1 -> s_h -> GEMM2 accumulate ----
    float d2[8][4];
    #pragma unroll
    for (int j = 0; j < 8; j++)
        #pragma unroll
        for (int c = 0; c < 4; c++) d2[j][c] = 0.f;

    #pragma unroll
    for (int P = 0; P < 2; P++) {
        {   // stage ff1 half P
            const float4* src = (const float4*)(g_ff1h + P*4608);
            float4* dst = (float4*)s_w;
            for (int i = tid; i < 1152; i += 256) dst[i] = src[i];
        }
        __syncthreads();
        float d1[8][4];
        #pragma unroll
        for (int j = 0; j < 8; j++)
            #pragma unroll
            for (int c = 0; c < 4; c++) d1[j][c] = 0.f;
        #pragma unroll
        for (int k0 = 0; k0 < 64; k0 += 8) {
            unsigned a[2][4];
            #pragma unroll
            for (int t = 0; t < 2; t++) {
                int mr = m0 + 16*t + gr;
                a[t][0] = so32[mr*68     + k0+tg];
                a[t][1] = so32[(mr+8)*68 + k0+tg];
                a[t][2] = so32[mr*68     + k0+tg+4];
                a[t][3] = so32[(mr+8)*68 + k0+tg+4];
            }
            #pragma unroll
            for (int j = 0; j < 4; j++) {
                int nn = wn*32 + j*8;
                unsigned b0 = sw32[(k0+tg)*72   + nn+gr];
                unsigned b1 = sw32[(k0+tg+4)*72 + nn+gr];
                #pragma unroll
                for (int t = 0; t < 2; t++)
                    mma_tf32(d1[t*4+j], a[t][0], a[t][1], a[t][2], a[t][3], b0, b1);
            }
        }
        __syncthreads();   // all warps done reading s_w(ff1)
        // write h half (local columns 0..63) + stage ff2 half P
        #pragma unroll
        for (int t = 0; t < 2; t++) {
            #pragma unroll
            for (int j = 0; j < 4; j++) {
                int nl = wn*32 + j*8 + 2*tg;
                int ng = P*64 + nl;
                int mr = m0 + 16*t + gr;
                float bb0 = s_m[256 + ng], bb1 = s_m[256 + ng + 1];
                *(float2*)&s_h[mr*68 + nl] = make_float2(
                    tf32r(fmaxf(d1[t*4+j][0] + bb0, 0.f)), tf32r(fmaxf(d1[t*4+j][1] + bb1, 0.f)));
                *(float2*)&s_h[(mr+8)*68 + nl] = make_float2(
                    tf32r(fmaxf(d1[t*4+j][2] + bb0, 0.f)), tf32r(fmaxf(d1[t*4+j][3] + bb1, 0.f)));
            }
        }
        {
            const float4* src = (const float4*)(g_ff2h + P*4608);
            float4* dst = (float4*)s_w;
            for (int i = tid; i < 1152; i += 256) dst[i] = src[i];
        }
        __syncthreads();
        // GEMM2 partial: d2 += h_P @ ff2_P
        #pragma unroll
        for (int k0 = 0; k0 < 64; k0 += 8) {
            unsigned a[2][4];
            #pragma unroll
            for (int t = 0; t < 2; t++) {
                int mr = m0 + 16*t + gr;
                a[t][0] = sh32[mr*68     + k0+tg];
                a[t][1] = sh32[(mr+8)*68 + k0+tg];
                a[t][2] = sh32[mr*68     + k0+tg+4];
                a[t][3] = sh32[(mr+8)*68 + k0+tg+4];
            }
            #pragma unroll
            for (int j = 0; j < 4; j++) {
                int nn = wn*32 + j*8;
                unsigned b0 = sw32[(k0+tg)*72   + nn+gr];
                unsigned b1 = sw32[(k0+tg+4)*72 + nn+gr];
                #pragma unroll
                for (int t = 0; t < 2; t++)
                    mma_tf32(d2[t*4+j], a[t][0], a[t][1], a[t][2], a[t][3], b0, b1);
            }
        }
        __syncthreads();   // before next P overwrites s_w / s_h
    }

    // ---- GEMM2 epilogue: o += d2 + b2 ----
    #pragma unroll
    for (int t = 0; t < 2; t++) {
        #pragma unroll
        for (int j = 0; j < 4; j++) {
            int n = wn*32 + j*8 + 2*tg;
            int mr = m0 + 16*t + gr;
            float bb0 = s_m[384 + n], bb1 = s_m[384 + n + 1];
            float2 o0 = *(float2*)&s_o[mr*68 + n];
            float2 o1 = *(float2*)&s_o[(mr+8)*68 + n];
            *(float2*)&s_o[mr*68 + n]     = make_float2(o0.x + d2[t*4+j][0] + bb0, o0.y + d2[t*4+j][1] + bb1);
            *(float2*)&s_o[(mr+8)*68 + n] = make_float2(o1.x + d2[t*4+j][2] + bb0, o1.y + d2[t*4+j][3] + bb1);
        }
    }
    __syncthreads();

    // ---- LN2 for both pixels; write tf32 ----
    #pragma unroll
    for (int rr = 0; rr < 2; rr++) {
        float* row = &s_o[(rr*64 + p)*68];
        float v2[16], m1 = 0.f, m2 = 0.f;
        #pragma unroll
        for (int i = 0; i < 4; i++) {
            float4 t4 = *(const float4*)&row[hd*16 + 4*i];
            v2[4*i+0] = t4.x; v2[4*i+1] = t4.y; v2[4*i+2] = t4.z; v2[4*i+3] = t4.w;
        }
        #pragma unroll
        for (int dd = 0; dd < 16; dd++) { m1 += v2[dd]; m2 = fmaf(v2[dd], v2[dd], m2); }
        m1 += __shfl_xor_sync(0xffffffff, m1, 1);
        m2 += __shfl_xor_sync(0xffffffff, m2, 1);
        m1 += __shfl_xor_sync(0xffffffff, m1, 2);
        m2 += __shfl_xor_sync(0xffffffff, m2, 2);
        const float mean = m1 * (1.f/64.f);
        const float var  = m2 * (1.f/64.f) - mean*mean;
        const float rstd = rsqrtf(var + 1e-3f);
        #pragma unroll
        for (int i = 0; i < 4; i++) {
            const int c = hd*16 + 4*i;
            float4 w4;
            w4.x = tf32r((v2[4*i+0] - mean)*rstd*s_m[128+c+0] + s_m[192+c+0]);
            w4.y = tf32r((v2[4*i+1] - mean)*rstd*s_m[128+c+1] + s_m[192+c+1]);
            w4.z = tf32r((v2[4*i+2] - mean)*rstd*s_m[128+c+2] + s_m[192+c+2]);
            w4.w = tf32r((v2[4*i+3] - mean)*rstd*s_m[128+c+3] + s_m[192+c+3]);
            *(float4*)&row[c] = w4;
        }
    }
    // stage fuse weights
    {
        const float4* src = (const float4*)g_wfuse72;
        float4* dst = (float4*)s_w;
        for (int i = tid; i < 1152; i += 256) dst[i] = src[i];
    }
    __syncthreads();

    // ---- GEMM3: fuse conv + BN + relu, direct global store ----
    {
        float d3[8][4];
        #pragma unroll
        for (int j = 0; j < 8; j++)
            #pragma unroll
            for (int c = 0; c < 4; c++) d3[j][c] = 0.f;
        #pragma unroll
        for (int k0 = 0; k0 < 64; k0 += 8) {
            unsigned a[2][4];
            #pragma unroll
            for (int t = 0; t < 2; t++) {
                int mr = m0 + 16*t + gr;
                a[t][0] = so32[mr*68     + k0+tg];
                a[t][1] = so32[(mr+8)*68 + k0+tg];
                a[t][2] = so32[mr*68     + k0+tg+4];
                a[t][3] = so32[(mr+8)*68 + k0+tg+4];
            }
            #pragma unroll
            for (int j = 0; j < 4; j++) {
                int nn = wn*32 + j*8;
                unsigned b0 = sw32[(k0+tg)*72   + nn+gr];
                unsigned b1 = sw32[(k0+tg+4)*72 + nn+gr];
                #pragma unroll
                for (int t = 0; t < 2; t++)
                    mma_tf32(d3[t*4+j], a[t][0], a[t][1], a[t][2], a[t][3], b0, b1);
            }
        }
        #pragma unroll
        for (int t = 0; t < 2; t++) {
            #pragma unroll
            for (int j = 0; j < 4; j++) {
                int n = wn*32 + j*8 + 2*tg;
                int mr = m0 + 16*t + gr;       // 0..127
                int ry = mr >> 6, mx = mr & 63;
                float sc0 = s_m[448 + n], sc1 = s_m[448 + n + 1];
                float sh0 = s_m[512 + n], sh1 = s_m[512 + n + 1];
                float* ob0 = out + ((b*HDIM + y0 + ry)*WDIM + c0 + mx)*64;
                float* ob1 = out + ((b*HDIM + y0 + ry)*WDIM + c0 + mx + 8)*64;
                *(float2*)&ob0[n] = make_float2(
                    fmaxf(d3[t*4+j][0]*sc0 + sh0, 0.f), fmaxf(d3[t*4+j][1]*sc1 + sh1, 0.f));
                *(float2*)&ob1[n] = make_float2(
                    fmaxf(d3[t*4+j][2]*sc0 + sh0, 0.f), fmaxf(d3[t*4+j][3]*sc1 + sh1, 0.f));
            }
        }
    }
}

extern "C" void kernel_launch(void* const* d_in, const int* in_sizes, int n_in,
                              void* d_out, int out_size)
{
    const float* x      = (const float*)d_in[0];
    const float* wq     = (const float*)d_in[1];
    const float* wk     = (const float*)d_in[2];
    const float* wv     = (const float*)d_in[3];
    const float* ln1_g  = (const float*)d_in[4];
    const float* ln1_b  = (const float*)d_in[5];
    const float* ff1_w  = (const float*)d_in[6];
    const float* ff1_b  = (const float*)d_in[7];
    const float* ff2_w  = (const float*)d_in[8];
    const float* ff2_b  = (const float*)d_in[9];
    const float* ln2_g  = (const float*)d_in[10];
    const float* ln2_b  = (const float*)d_in[11];
    const float* w_fuse = (const float*)d_in[12];
    const float* bn_g   = (const float*)d_in[13];
    const float* bn_b   = (const float*)d_in[14];
    const float* bn_mean= (const float*)d_in[15];
    const float* bn_var = (const float*)d_in[16];
    float* out = (float*)d_out;

    const int SMEM_A = (12800 + 64*68) * 4;   // 68608 B
    const int SMEM_B = SMB_FLOATS * 4;        // 108928 B
    cudaFuncSetAttribute(qkv_kernel, cudaFuncAttributeMaxDynamicSharedMemorySize, SMEM_A);
    cudaFuncSetAttribute(attn_ffn_kernel, cudaFuncAttributeMaxDynamicSharedMemorySize, SMEM_B);

    cvt_weights_kernel<<<140, 256>>>(wq, wk, wv, ff1_w, ff2_w, w_fuse);
    qkv_kernel<<<NPIX/64, 256, SMEM_A>>>(x);

    dim3 grid(WDIM/64, HDIM/2, BATCH);
    attn_ffn_kernel<<<grid, 256, SMEM_B>>>(
        x, ln1_g, ln1_b, ff1_b, ff2_b,
        ln2_g, ln2_b, bn_g, bn_b, bn_mean, bn_var, out);
}

// round 7
// speedup vs baseline: 1.9351x; 1.3464x over previous
#include <cuda_runtime.h>

#define BATCH 4
#define HDIM 384
#define WDIM 384
#define NPIX (BATCH*HDIM*WDIM)

__device__ float g_q[NPIX*64];
__device__ float g_k[NPIX*64];
__device__ float g_v[NPIX*64];
// Pre-converted tf32 weights in smem-ready padded layouts
__device__ float g_wqkv[64*200];      // [k][200]: wq|wk|wv
__device__ float g_ff1h[2*64*72];     // half P: [k][72]
__device__ float g_ff2h[2*64*72];     // half Kp: [k][72]
__device__ float g_wfuse72[64*72];    // [k][72]

__device__ __forceinline__ float tf32r(float x) {
    unsigned u;
    asm("cvt.rna.tf32.f32 %0, %1;" : "=r"(u) : "f"(x));
    return __uint_as_float(u);
}

__device__ __forceinline__ void mma_tf32(float* d,
    unsigned a0, unsigned a1, unsigned a2, unsigned a3,
    unsigned b0, unsigned b1)
{
    asm volatile("mma.sync.aligned.m16n8k8.row.col.f32.tf32.tf32.f32 "
        "{%0,%1,%2,%3}, {%4,%5,%6,%7}, {%8,%9}, {%0,%1,%2,%3};"
        : "+f"(d[0]), "+f"(d[1]), "+f"(d[2]), "+f"(d[3])
        : "r"(a0), "r"(a1), "r"(a2), "r"(a3), "r"(b0), "r"(b1));
}

__device__ __forceinline__ unsigned sptr(const void* p) {
    return (unsigned)__cvta_generic_to_shared((void*)p);
}
#define CP16(dst, src, sz) \
    asm volatile("cp.async.cg.shared.global [%0], [%1], 16, %2;" \
                 :: "r"(dst), "l"(src), "r"(sz))
#define CP_COMMIT asm volatile("cp.async.commit_group;" ::: "memory")
#define CP_WAIT0  asm volatile("cp.async.wait_group 0;"  ::: "memory")

// XOR swizzle: for column c in [0,64), rows with stride 68
#define SWZ(row, c) ((c) ^ (((row) & 3) << 4))

// ---------------------------------------------------------------------------
// One-time weight prep
// ---------------------------------------------------------------------------
__global__ void __launch_bounds__(256) cvt_weights_kernel(
    const float* __restrict__ wq, const float* __restrict__ wk,
    const float* __restrict__ wv, const float* __restrict__ ff1_w,
    const float* __restrict__ ff2_w, const float* __restrict__ w_fuse)
{
    int i = blockIdx.x*256 + threadIdx.x;
    if (i < 12800) {
        int k = i / 200, n = i % 200;
        float v = 0.f;
        if (n < 64)       v = tf32r(wq[k*64 + n]);
        else if (n < 128) v = tf32r(wk[k*64 + n - 64]);
        else if (n < 192) v = tf32r(wv[k*64 + n - 128]);
        g_wqkv[i] = v;
        return;
    }
    i -= 12800;
    if (i < 9216) {
        int P = i / 4608, r = i % 4608, k = r / 72, n = r % 72;
        g_ff1h[i] = (n < 64) ? tf32r(ff1_w[k*128 + P*64 + n]) : 0.f;
        return;
    }
    i -= 9216;
    if (i < 9216) {
        int Kp = i / 4608, r = i % 4608, k = r / 72, n = r % 72;
        g_ff2h[i] = (n < 64) ? tf32r(ff2_w[(Kp*64 + k)*64 + n]) : 0.f;
        return;
    }
    i -= 9216;
    if (i < 4608) {
        int k = i / 72, n = i % 72;
        g_wfuse72[i] = (n < 64) ? tf32r(w_fuse[k*64 + n]) : 0.f;
    }
}

// ---------------------------------------------------------------------------
// Kernel A: qkv projection. 128 px/block, 512 threads, warp tile 32m x 48n.
// ws [64][200] staged via cp.async; xs [128][68] (tf32-rounded).
// ---------------------------------------------------------------------------
__global__ void __launch_bounds__(512,1) qkv_kernel(const float* __restrict__ x)
{
    extern __shared__ float sm[];
    float* ws = sm;            // [64][200]
    float* xs = sm + 12800;    // [128][68]
    const int tid = threadIdx.x;

    {
        const float4* src = (const float4*)g_wqkv;
        unsigned base = sptr(ws);
        for (int i = tid; i < 3200; i += 512) CP16(base + i*16, src + i, 16);
        CP_COMMIT;
    }
    const int pix0 = blockIdx.x * 128;
    const float4* xg = (const float4*)(x + pix0*64);
    for (int i = tid; i < 2048; i += 512) {
        int m = i >> 4, c4 = i & 15;
        float4 v = xg[i];
        v.x = tf32r(v.x); v.y = tf32r(v.y); v.z = tf32r(v.z); v.w = tf32r(v.w);
        *(float4*)&xs[m*68 + c4*4] = v;
    }
    CP_WAIT0;
    __syncthreads();

    const int wid = tid >> 5, lane = tid & 31;
    const int gr = lane >> 2, tg = lane & 3;
    const int m0 = (wid >> 2) * 32;
    const int n0 = (wid & 3) * 48;
    const unsigned* xs32 = (const unsigned*)xs;
    const unsigned* ws32 = (const unsigned*)ws;

    float d[12][4];
    #pragma unroll
    for (int j = 0; j < 12; j++)
        #pragma unroll
        for (int c = 0; c < 4; c++) d[j][c] = 0.f;

    #pragma unroll
    for (int k0 = 0; k0 < 64; k0 += 8) {
        unsigned a[2][4];
        #pragma unroll
        for (int t = 0; t < 2; t++) {
            int mr = m0 + 16*t + gr;
            a[t][0] = xs32[mr*68      + k0+tg];
            a[t][1] = xs32[(mr+8)*68  + k0+tg];
            a[t][2] = xs32[mr*68      + k0+tg+4];
            a[t][3] = xs32[(mr+8)*68  + k0+tg+4];
        }
        #pragma unroll
        for (int j = 0; j < 6; j++) {
            int nn = n0 + j*8;
            unsigned b0 = ws32[(k0+tg)*200   + nn+gr];
            unsigned b1 = ws32[(k0+tg+4)*200 + nn+gr];
            #pragma unroll
            for (int t = 0; t < 2; t++)
                mma_tf32(d[t*6+j], a[t][0], a[t][1], a[t][2], a[t][3], b0, b1);
        }
    }

    #pragma unroll
    for (int t = 0; t < 2; t++) {
        #pragma unroll
        for (int j = 0; j < 6; j++) {
            int n = n0 + j*8 + 2*tg;
            float* dst; int nn;
            if (n < 64)       { dst = g_q; nn = n; }
            else if (n < 128) { dst = g_k; nn = n - 64; }
            else              { dst = g_v; nn = n - 128; }
            int m = pix0 + m0 + 16*t + gr;
            *(float2*)&dst[m*64 + nn]     = make_float2(d[t*6+j][0], d[t*6+j][1]);
            *(float2*)&dst[(m+8)*64 + nn] = make_float2(d[t*6+j][2], d[t*6+j][3]);
        }
    }
}

// ---------------------------------------------------------------------------
// Kernel B: 2 image rows (128 px)/block, 256 threads, 2 blocks/SM.
// cp.async staging everywhere; XOR-swizzled halo/s_o/s_h (conflict-free).
// smem layout (floats) unchanged from r6: total 27232.
// ---------------------------------------------------------------------------
#define R2OFF 17952
#define MOFF  26656
#define SMB_FLOATS 27232

__global__ void __launch_bounds__(256,2) attn_ffn_kernel(
    const float* __restrict__ x,
    const float* __restrict__ ln1_g, const float* __restrict__ ln1_b,
    const float* __restrict__ ff1_b,
    const float* __restrict__ ff2_b,
    const float* __restrict__ ln2_g, const float* __restrict__ ln2_b,
    const float* __restrict__ bn_g, const float* __restrict__ bn_b,
    const float* __restrict__ bn_mean, const float* __restrict__ bn_var,
    float* __restrict__ out)
{
    extern __shared__ float sm[];
    float* s_halo = sm;               // [264][68], swizzled
    float* s_w    = sm;               // [64][72], linear (aliases halo)
    float* s_h    = sm + 4608;        // [128][68], swizzled
    float* s_o    = sm + R2OFF;       // [128][68], swizzled
    float* s_m    = sm + MOFF;

    const int tid = threadIdx.x;

    const int b  = blockIdx.z;
    const int y0 = blockIdx.y * 2;
    const int c0 = blockIdx.x * 64;

    // ---- issue k-halo cp.async (swizzled dst, zfill boundary) ----
    #pragma unroll
    for (int r = 0; r < 4; r++) {
        const int gy = y0 + r - 1;
        const bool rowok = (unsigned)gy < HDIM;
        const float* src = g_k + (((long)b*HDIM + gy)*WDIM + c0 - 1)*64;
        for (int idx = tid; idx < 1056; idx += 256) {
            int j = idx >> 4, c4 = idx & 15;
            int gx = c0 + j - 1;
            int row = r*66 + j;
            int off = row*68 + SWZ(row, c4*4);
            int sz = (rowok && (unsigned)gx < WDIM) ? 16 : 0;
            CP16(sptr(s_halo + off), src + j*64 + c4*4, sz);
        }
    }
    CP_COMMIT;

    if (tid < 64) {
        s_m[tid]        = ln1_g[tid];
        s_m[64 + tid]   = ln1_b[tid];
        s_m[128 + tid]  = ln2_g[tid];
        s_m[192 + tid]  = ln2_b[tid];
        s_m[384 + tid]  = ff2_b[tid];
        float sc = bn_g[tid] * rsqrtf(bn_var[tid] + 1e-3f);
        s_m[448 + tid]  = sc;
        s_m[512 + tid]  = bn_b[tid] - bn_mean[tid]*sc;
    } else if (tid < 192) {
        s_m[256 + (tid - 64)] = ff1_b[tid - 64];
    }

    const int p  = tid >> 2;
    const int hd = tid & 3;
    const int base0 = ((b*HDIM + y0)*WDIM + c0 + p)*64;
    const int base1 = base0 + WDIM*64;

    float q0[16], q1[16];
    #pragma unroll
    for (int i = 0; i < 4; i++) {
        *(float4*)&q0[4*i] = *(const float4*)(g_q + base0 + hd*16 + 4*i);
        *(float4*)&q1[4*i] = *(const float4*)(g_q + base1 + hd*16 + 4*i);
    }
    CP_WAIT0;
    __syncthreads();

    // ---- scores for both rows (swizzled halo reads) ----
    float s0[9], s1[9];
    #pragma unroll
    for (int r = 0; r < 4; r++) {
        #pragma unroll
        for (int dx = 0; dx < 3; dx++) {
            int row = r*66 + p + dx;
            const float* kp = &s_halo[row*68 + ((hd ^ (row & 3)) << 4)];
            float kk[16];
            #pragma unroll
            for (int i = 0; i < 4; i++) *(float4*)&kk[4*i] = *(const float4*)&kp[4*i];
            if (r < 3) {
                float s = 0.f;
                #pragma unroll
                for (int dd = 0; dd < 16; dd++) s = fmaf(q0[dd], kk[dd], s);
                s0[r*3 + dx] = s * 0.25f;
            }
            if (r > 0) {
                float s = 0.f;
                #pragma unroll
                for (int dd = 0; dd < 16; dd++) s = fmaf(q1[dd], kk[dd], s);
                s1[(r-1)*3 + dx] = s * 0.25f;
            }
        }
    }
    float mx0 = s0[0], mx1 = s1[0];
    #pragma unroll
    for (int o = 1; o < 9; o++) { mx0 = fmaxf(mx0, s0[o]); mx1 = fmaxf(mx1, s1[o]); }
    float sum0 = 0.f, sum1 = 0.f;
    #pragma unroll
    for (int o = 0; o < 9; o++) {
        s0[o] = __expf(s0[o] - mx0); sum0 += s0[o];
        s1[o] = __expf(s1[o] - mx1); sum1 += s1[o];
    }
    const float si0 = 1.f/sum0, si1 = 1.f/sum1;
    #pragma unroll
    for (int o = 0; o < 9; o++) { s0[o] *= si0; s1[o] *= si1; }

    __syncthreads();   // all k-halo reads done

    // ---- issue v-halo cp.async ----
    #pragma unroll
    for (int r = 0; r < 4; r++) {
        const int gy = y0 + r - 1;
        const bool rowok = (unsigned)gy < HDIM;
        const float* src = g_v + (((long)b*HDIM + gy)*WDIM + c0 - 1)*64;
        for (int idx = tid; idx < 1056; idx += 256) {
            int j = idx >> 4, c4 = idx & 15;
            int gx = c0 + j - 1;
            int row = r*66 + j;
            int off = row*68 + SWZ(row, c4*4);
            int sz = (rowok && (unsigned)gx < WDIM) ? 16 : 0;
            CP16(sptr(s_halo + off), src + j*64 + c4*4, sz);
        }
    }
    CP_COMMIT;

    float xr0[16], xr1[16];
    #pragma unroll
    for (int i = 0; i < 4; i++) {
        *(float4*)&xr0[4*i] = *(const float4*)(x + base0 + hd*16 + 4*i);
        *(float4*)&xr1[4*i] = *(const float4*)(x + base1 + hd*16 + 4*i);
    }
    CP_WAIT0;
    __syncthreads();

    // ---- weighted v sums for both rows ----
    float a0[16], a1[16];
    #pragma unroll
    for (int dd = 0; dd < 16; dd++) { a0[dd] = 0.f; a1[dd] = 0.f; }
    #pragma unroll
    for (int r = 0; r < 4; r++) {
        #pragma unroll
        for (int dx = 0; dx < 3; dx++) {
            int row = r*66 + p + dx;
            const float* vp = &s_halo[row*68 + ((hd ^ (row & 3)) << 4)];
            float vv[16];
            #pragma unroll
            for (int i = 0; i < 4; i++) *(float4*)&vv[4*i] = *(const float4*)&vp[4*i];
            if (r < 3) {
                const float w = s0[r*3 + dx];
                #pragma unroll
                for (int dd = 0; dd < 16; dd++) a0[dd] = fmaf(w, vv[dd], a0[dd]);
            }
            if (r > 0) {
                const float w = s1[(r-1)*3 + dx];
                #pragma unroll
                for (int dd = 0; dd < 16; dd++) a1[dd] = fmaf(w, vv[dd], a1[dd]);
            }
        }
    }

    // ---- LN1 (+residual); tf32 into swizzled s_o ----
    #pragma unroll
    for (int rr = 0; rr < 2; rr++) {
        float* av = rr ? a1 : a0;
        float* xv = rr ? xr1 : xr0;
        float m1 = 0.f, m2 = 0.f;
        #pragma unroll
        for (int dd = 0; dd < 16; dd++) {
            av[dd] += xv[dd];
            m1 += av[dd];
            m2 = fmaf(av[dd], av[dd], m2);
        }
        m1 += __shfl_xor_sync(0xffffffff, m1, 1);
        m2 += __shfl_xor_sync(0xffffffff, m2, 1);
        m1 += __shfl_xor_sync(0xffffffff, m1, 2);
        m2 += __shfl_xor_sync(0xffffffff, m2, 2);
        const float mean = m1 * (1.f/64.f);
        const float var  = m2 * (1.f/64.f) - mean*mean;
        const float rstd = rsqrtf(var + 1e-3f);
        int row = rr*64 + p;
        float* dst = &s_o[row*68 + ((hd ^ (row & 3)) << 4)];
        #pragma unroll
        for (int i = 0; i < 4; i++) {
            const int c = hd*16 + 4*i;
            float4 w4;
            w4.x = tf32r((av[4*i+0] - mean)*rstd*s_m[c+0] + s_m[64+c+0]);
            w4.y = tf32r((av[4*i+1] - mean)*rstd*s_m[c+1] + s_m[64+c+1]);
            w4.z = tf32r((av[4*i+2] - mean)*rstd*s_m[c+2] + s_m[64+c+2]);
            w4.w = tf32r((av[4*i+3] - mean)*rstd*s_m[c+3] + s_m[64+c+3]);
            *(float4*)&dst[4*i] = w4;
        }
    }
    __syncthreads();   // halo dead; LN1 visible

    const int wid = tid >> 5, lane = tid & 31;
    const int gr = lane >> 2, tg = lane & 3;
    const int m0 = (wid >> 1) * 32;
    const int wn = wid & 1;
    const unsigned* so32 = (const unsigned*)s_o;
    const unsigned* sh32 = (const unsigned*)s_h;
    const unsigned* sw32 = (const unsigned*)s_w;

    // ---- fused FFN: per half P: GEMM1 -> s_h -> GEMM2 accumulate ----
    float d2[8][4];
    #pragma unroll
    for (int j = 0; j < 8; j++)
        #pragma unroll
        for (int c = 0; c < 4; c++) d2[j][c] = 0.f;

    #pragma unroll
    for (int P = 0; P < 2; P++) {
        {   // stage ff1 half P (cp.async)
            const float4* src = (const float4*)(g_ff1h + P*4608);
            unsigned base = sptr(s_w);
            for (int i = tid; i < 1152; i += 256) CP16(base + i*16, src + i, 16);
            CP_COMMIT;
        }
        CP_WAIT0;
        __syncthreads();
        float d1[8][4];
        #pragma unroll
        for (int j = 0; j < 8; j++)
            #pragma unroll
            for (int c = 0; c < 4; c++) d1[j][c] = 0.f;
        #pragma unroll
        for (int k0 = 0; k0 < 64; k0 += 8) {
            unsigned a[2][4];
            #pragma unroll
            for (int t = 0; t < 2; t++) {
                int mr = m0 + 16*t + gr;
                int xo = mr*68 + ((k0+tg) ^ ((mr & 3) << 4));
                a[t][0] = so32[xo];
                a[t][2] = so32[xo+4];
                a[t][1] = so32[xo + 8*68];
                a[t][3] = so32[xo + 8*68 + 4];
            }
            #pragma unroll
            for (int j = 0; j < 4; j++) {
                int nn = wn*32 + j*8;
                unsigned b0 = sw32[(k0+tg)*72   + nn+gr];
                unsigned b1 = sw32[(k0+tg+4)*72 + nn+gr];
                #pragma unroll
                for (int t = 0; t < 2; t++)
                    mma_tf32(d1[t*4+j], a[t][0], a[t][1], a[t][2], a[t][3], b0, b1);
            }
        }
        __syncthreads();   // all warps done reading s_w(ff1); s_h free
        {   // stage ff2 half P (cp.async) — overlaps h writes below
            const float4* src = (const float4*)(g_ff2h + P*4608);
            unsigned base = sptr(s_w);
            for (int i = tid; i < 1152; i += 256) CP16(base + i*16, src + i, 16);
            CP_COMMIT;
        }
        // write h half into swizzled s_h
        #pragma unroll
        for (int t = 0; t < 2; t++) {
            #pragma unroll
            for (int j = 0; j < 4; j++) {
                int nl = wn*32 + j*8 + 2*tg;
                int ng = P*64 + nl;
                int mr = m0 + 16*t + gr;
                float bb0 = s_m[256 + ng], bb1 = s_m[256 + ng + 1];
                int off = mr*68 + (nl ^ ((mr & 3) << 4));
                *(float2*)&s_h[off] = make_float2(
                    tf32r(fmaxf(d1[t*4+j][0] + bb0, 0.f)), tf32r(fmaxf(d1[t*4+j][1] + bb1, 0.f)));
                *(float2*)&s_h[off + 8*68] = make_float2(
                    tf32r(fmaxf(d1[t*4+j][2] + bb0, 0.f)), tf32r(fmaxf(d1[t*4+j][3] + bb1, 0.f)));
            }
        }
        CP_WAIT0;
        __syncthreads();
        // GEMM2 partial: d2 += h_P @ ff2_P
        #pragma unroll
        for (int k0 = 0; k0 < 64; k0 += 8) {
            unsigned a[2][4];
            #pragma unroll
            for (int t = 0; t < 2; t++) {
                int mr = m0 + 16*t + gr;
                int xo = mr*68 + ((k0+tg) ^ ((mr & 3) << 4));
                a[t][0] = sh32[xo];
                a[t][2] = sh32[xo+4];
                a[t][1] = sh32[xo + 8*68];
                a[t][3] = sh32[xo + 8*68 + 4];
            }
            #pragma unroll
            for (int j = 0; j < 4; j++) {
                int nn = wn*32 + j*8;
                unsigned b0 = sw32[(k0+tg)*72   + nn+gr];
                unsigned b1 = sw32[(k0+tg+4)*72 + nn+gr];
                #pragma unroll
                for (int t = 0; t < 2; t++)
                    mma_tf32(d2[t*4+j], a[t][0], a[t][1], a[t][2], a[t][3], b0, b1);
            }
        }
        __syncthreads();   // before next P overwrites s_w / s_h
    }

    // ---- GEMM2 epilogue: o += d2 + b2 (swizzled s_o) ----
    #pragma unroll
    for (int t = 0; t < 2; t++) {
        #pragma unroll
        for (int j = 0; j < 4; j++) {
            int n = wn*32 + j*8 + 2*tg;
            int mr = m0 + 16*t + gr;
            float bb0 = s_m[384 + n], bb1 = s_m[384 + n + 1];
            int off = mr*68 + (n ^ ((mr & 3) << 4));
            float2 o0 = *(float2*)&s_o[off];
            float2 o1 = *(float2*)&s_o[off + 8*68];
            *(float2*)&s_o[off]        = make_float2(o0.x + d2[t*4+j][0] + bb0, o0.y + d2[t*4+j][1] + bb1);
            *(float2*)&s_o[off + 8*68] = make_float2(o1.x + d2[t*4+j][2] + bb0, o1.y + d2[t*4+j][3] + bb1);
        }
    }
    __syncthreads();

    // stage fuse weights early (s_w free); loads overlap LN2 math
    {
        const float4* src = (const float4*)g_wfuse72;
        unsigned base = sptr(s_w);
        for (int i = tid; i < 1152; i += 256) CP16(base + i*16, src + i, 16);
        CP_COMMIT;
    }

    // ---- LN2 for both pixels (swizzled s_o, own slots) ----
    #pragma unroll
    for (int rr = 0; rr < 2; rr++) {
        int row = rr*64 + p;
        float* rp = &s_o[row*68 + ((hd ^ (row & 3)) << 4)];
        float v2[16], m1 = 0.f, m2 = 0.f;
        #pragma unroll
        for (int i = 0; i < 4; i++) {
            float4 t4 = *(const float4*)&rp[4*i];
            v2[4*i+0] = t4.x; v2[4*i+1] = t4.y; v2[4*i+2] = t4.z; v2[4*i+3] = t4.w;
        }
        #pragma unroll
        for (int dd = 0; dd < 16; dd++) { m1 += v2[dd]; m2 = fmaf(v2[dd], v2[dd], m2); }
        m1 += __shfl_xor_sync(0xffffffff, m1, 1);
        m2 += __shfl_xor_sync(0xffffffff, m2, 1);
        m1 += __shfl_xor_sync(0xffffffff, m1, 2);
        m2 += __shfl_xor_sync(0xffffffff, m2, 2);
        const float mean = m1 * (1.f/64.f);
        const float var  = m2 * (1.f/64.f) - mean*mean;
        const float rstd = rsqrtf(var + 1e-3f);
        #pragma unroll
        for (int i = 0; i < 4; i++) {
            const int c = hd*16 + 4*i;
            float4 w4;
            w4.x = tf32r((v2[4*i+0] - mean)*rstd*s_m[128+c+0] + s_m[192+c+0]);
            w4.y = tf32r((v2[4*i+1] - mean)*rstd*s_m[128+c+1] + s_m[192+c+1]);
            w4.z = tf32r((v2[4*i+2] - mean)*rstd*s_m[128+c+2] + s_m[192+c+2]);
            w4.w = tf32r((v2[4*i+3] - mean)*rstd*s_m[128+c+3] + s_m[192+c+3]);
            *(float4*)&rp[4*i] = w4;
        }
    }
    CP_WAIT0;
    __syncthreads();

    // ---- GEMM3: fuse conv + BN + relu, direct global store ----
    {
        float d3[8][4];
        #pragma unroll
        for (int j = 0; j < 8; j++)
            #pragma unroll
            for (int c = 0; c < 4; c++) d3[j][c] = 0.f;
        #pragma unroll
        for (int k0 = 0; k0 < 64; k0 += 8) {
            unsigned a[2][4];
            #pragma unroll
            for (int t = 0; t < 2; t++) {
                int mr = m0 + 16*t + gr;
                int xo = mr*68 + ((k0+tg) ^ ((mr & 3) << 4));
                a[t][0] = so32[xo];
                a[t][2] = so32[xo+4];
                a[t][1] = so32[xo + 8*68];
                a[t][3] = so32[xo + 8*68 + 4];
            }
            #pragma unroll
            for (int j = 0; j < 4; j++) {
                int nn = wn*32 + j*8;
                unsigned b0 = sw32[(k0+tg)*72   + nn+gr];
                unsigned b1 = sw32[(k0+tg+4)*72 + nn+gr];
                #pragma unroll
                for (int t = 0; t < 2; t++)
                    mma_tf32(d3[t*4+j], a[t][0], a[t][1], a[t][2], a[t][3], b0, b1);
            }
        }
        #pragma unroll
        for (int t = 0; t < 2; t++) {
            #pragma unroll
            for (int j = 0; j < 4; j++) {
                int n = wn*32 + j*8 + 2*tg;
                int mr = m0 + 16*t + gr;
                int ry = mr >> 6, mx = mr & 63;
                float sc0 = s_m[448 + n], sc1 = s_m[448 + n + 1];
                float sh0 = s_m[512 + n], sh1 = s_m[512 + n + 1];
                float* ob0 = out + ((b*HDIM + y0 + ry)*WDIM + c0 + mx)*64;
                float* ob1 = out + ((b*HDIM + y0 + ry)*WDIM + c0 + mx + 8)*64;
                *(float2*)&ob0[n] = make_float2(
                    fmaxf(d3[t*4+j][0]*sc0 + sh0, 0.f), fmaxf(d3[t*4+j][1]*sc1 + sh1, 0.f));
                *(float2*)&ob1[n] = make_float2(
                    fmaxf(d3[t*4+j][2]*sc0 + sh0, 0.f), fmaxf(d3[t*4+j][3]*sc1 + sh1, 0.f));
            }
        }
    }
}

extern "C" void kernel_launch(void* const* d_in, const int* in_sizes, int n_in,
                              void* d_out, int out_size)
{
    const float* x      = (const float*)d_in[0];
    const float* wq     = (const float*)d_in[1];
    const float* wk     = (const float*)d_in[2];
    const float* wv     = (const float*)d_in[3];
    const float* ln1_g  = (const float*)d_in[4];
    const float* ln1_b  = (const float*)d_in[5];
    const float* ff1_w  = (const float*)d_in[6];
    const float* ff1_b  = (const float*)d_in[7];
    const float* ff2_w  = (const float*)d_in[8];
    const float* ff2_b  = (const float*)d_in[9];
    const float* ln2_g  = (const float*)d_in[10];
    const float* ln2_b  = (const float*)d_in[11];
    const float* w_fuse = (const float*)d_in[12];
    const float* bn_g   = (const float*)d_in[13];
    const float* bn_b   = (const float*)d_in[14];
    const float* bn_mean= (const float*)d_in[15];
    const float* bn_var = (const float*)d_in[16];
    float* out = (float*)d_out;

    const int SMEM_A = (12800 + 128*68) * 4;  // 86016 B
    const int SMEM_B = SMB_FLOATS * 4;        // 108928 B
    cudaFuncSetAttribute(qkv_kernel, cudaFuncAttributeMaxDynamicSharedMemorySize, SMEM_A);
    cudaFuncSetAttribute(attn_ffn_kernel, cudaFuncAttributeMaxDynamicSharedMemorySize, SMEM_B);

    cvt_weights_kernel<<<140, 256>>>(wq, wk, wv, ff1_w, ff2_w, w_fuse);
    qkv_kernel<<<NPIX/128, 512, SMEM_A>>>(x);

    dim3 grid(WDIM/64, HDIM/2, BATCH);
    attn_ffn_kernel<<<grid, 256, SMEM_B>>>(
        x, ln1_g, ln1_b, ff1_b, ff2_b,
        ln2_g, ln2_b, bn_g, bn_b, bn_mean, bn_var, out);
}

// round 8
// speedup vs baseline: 2.3594x; 1.2193x over previous
#include <cuda_runtime.h>
#include <cuda_fp16.h>

#define BATCH 4
#define HDIM 384
#define WDIM 384
#define NPIX (BATCH*HDIM*WDIM)

__device__ float g_q[NPIX*64];
__device__ float g_k[NPIX*64];
__device__ float g_v[NPIX*64];
// Pre-converted fp16 weights, B-operand layout [n][k] padded to 72
__device__ __half g_wqkv_h[192*72];   // n: 0..63 wq | 64..127 wk | 128..191 wv
__device__ __half g_ff1n[128*72];     // [n][k]  k<64 valid
__device__ __half g_ff2n[2*64*72];    // [P][n][k_local]
__device__ __half g_wfusen[64*72];    // [n][k]

__device__ __forceinline__ void mma_f16(float* d,
    unsigned a0, unsigned a1, unsigned a2, unsigned a3,
    unsigned b0, unsigned b1)
{
    asm volatile("mma.sync.aligned.m16n8k16.row.col.f32.f16.f16.f32 "
        "{%0,%1,%2,%3}, {%4,%5,%6,%7}, {%8,%9}, {%0,%1,%2,%3};"
        : "+f"(d[0]), "+f"(d[1]), "+f"(d[2]), "+f"(d[3])
        : "r"(a0), "r"(a1), "r"(a2), "r"(a3), "r"(b0), "r"(b1));
}

__device__ __forceinline__ unsigned sptr(const void* p) {
    return (unsigned)__cvta_generic_to_shared((void*)p);
}
#define CP16(dst, src, sz) \
    asm volatile("cp.async.cg.shared.global [%0], [%1], 16, %2;" \
                 :: "r"(dst), "l"(src), "r"(sz))
#define CP_COMMIT asm volatile("cp.async.commit_group;" ::: "memory")
#define CP_WAIT0  asm volatile("cp.async.wait_group 0;"  ::: "memory")

// fp32 halo swizzle (16-float groups)
#define SWZ(row, c) ((c) ^ (((row) & 3) << 4))

// ---------------------------------------------------------------------------
// One-time weight prep into fp16 [n][k] layouts (36864 elements)
// ---------------------------------------------------------------------------
__global__ void __launch_bounds__(256) cvt_weights_kernel(
    const float* __restrict__ wq, const float* __restrict__ wk,
    const float* __restrict__ wv, const float* __restrict__ ff1_w,
    const float* __restrict__ ff2_w, const float* __restrict__ w_fuse)
{
    int i = blockIdx.x*256 + threadIdx.x;
    if (i < 13824) {
        int n = i / 72, k = i % 72;
        float v = 0.f;
        if (k < 64) {
            if (n < 64)       v = wq[k*64 + n];
            else if (n < 128) v = wk[k*64 + n - 64];
            else              v = wv[k*64 + n - 128];
        }
        g_wqkv_h[i] = __float2half_rn(v);
        return;
    }
    i -= 13824;
    if (i < 9216) {
        int n = i / 72, k = i % 72;
        g_ff1n[i] = __float2half_rn(k < 64 ? ff1_w[k*128 + n] : 0.f);
        return;
    }
    i -= 9216;
    if (i < 9216) {
        int P = i / 4608, r = i % 4608, n = r / 72, k = r % 72;
        g_ff2n[i] = __float2half_rn(k < 64 ? ff2_w[(P*64 + k)*64 + n] : 0.f);
        return;
    }
    i -= 9216;
    if (i < 4608) {
        int n = i / 72, k = i % 72;
        g_wfusen[i] = __float2half_rn(k < 64 ? w_fuse[k*64 + n] : 0.f);
    }
}

// ---------------------------------------------------------------------------
// Kernel A: qkv = x @ [wq|wk|wv], fp16 mma. 128 px/block, 512 threads.
// ws half [192][72] (B, [n][k]); xs half [128][72] swizzled (A).
// ---------------------------------------------------------------------------
__global__ void __launch_bounds__(512,1) qkv_kernel(const float* __restrict__ x)
{
    extern __shared__ char smc[];
    __half* ws = (__half*)smc;              // 27648 B
    __half* xs = (__half*)(smc + 27648);    // 18432 B
    const int tid = threadIdx.x;

    {
        const char* src = (const char*)g_wqkv_h;
        unsigned base = sptr(ws);
        for (int i = tid; i < 1728; i += 512) CP16(base + i*16, src + i*16, 16);
        CP_COMMIT;
    }
    const int pix0 = blockIdx.x * 128;
    const float4* xg = (const float4*)(x + pix0*64);
    for (int i = tid; i < 2048; i += 512) {
        int m = i >> 4, c4 = i & 15;
        float4 v = xg[i];
        int col = (4*c4) ^ ((m & 3) << 4);
        __half2* d = (__half2*)&xs[m*72 + col];
        d[0] = __floats2half2_rn(v.x, v.y);
        d[1] = __floats2half2_rn(v.z, v.w);
    }
    CP_WAIT0;
    __syncthreads();

    const int wid = tid >> 5, lane = tid & 31;
    const int gr = lane >> 2, tg = lane & 3;
    const int m0 = (wid >> 2) * 32;
    const int n0 = (wid & 3) * 48;
    const unsigned* xsU = (const unsigned*)xs;
    const unsigned* wsU = (const unsigned*)ws;

    float d[12][4];
    #pragma unroll
    for (int j = 0; j < 12; j++)
        #pragma unroll
        for (int c = 0; c < 4; c++) d[j][c] = 0.f;

    #pragma unroll
    for (int k0 = 0; k0 < 64; k0 += 16) {
        const int kc = k0 >> 1;   // u32 col base
        unsigned a[2][4];
        #pragma unroll
        for (int t = 0; t < 2; t++) {
            int mr = m0 + 16*t + gr;
            int sw = (mr & 3) << 3;
            int base = mr*36;
            a[t][0] = xsU[base       + ((kc+tg)   ^ sw)];
            a[t][1] = xsU[base + 288 + ((kc+tg)   ^ sw)];
            a[t][2] = xsU[base       + ((kc+tg+4) ^ sw)];
            a[t][3] = xsU[base + 288 + ((kc+tg+4) ^ sw)];
        }
        #pragma unroll
        for (int j = 0; j < 6; j++) {
            int nn = n0 + j*8;
            unsigned b0 = wsU[(nn+gr)*36 + kc+tg];
            unsigned b1 = wsU[(nn+gr)*36 + kc+tg+4];
            #pragma unroll
            for (int t = 0; t < 2; t++)
                mma_f16(d[t*6+j], a[t][0], a[t][1], a[t][2], a[t][3], b0, b1);
        }
    }

    #pragma unroll
    for (int t = 0; t < 2; t++) {
        #pragma unroll
        for (int j = 0; j < 6; j++) {
            int n = n0 + j*8 + 2*tg;
            float* dst; int nn;
            if (n < 64)       { dst = g_q; nn = n; }
            else if (n < 128) { dst = g_k; nn = n - 64; }
            else              { dst = g_v; nn = n - 128; }
            int m = pix0 + m0 + 16*t + gr;
            *(float2*)&dst[m*64 + nn]     = make_float2(d[t*6+j][0], d[t*6+j][1]);
            *(float2*)&dst[(m+8)*64 + nn] = make_float2(d[t*6+j][2], d[t*6+j][3]);
        }
    }
}

// ---------------------------------------------------------------------------
// Kernel B: attention fp32 + fp16-MMA FFN/fuse. 128 px/block, 256 thr, 2/SM.
// smem bytes:
//   [0,71808)      halo fp32 [264][68] (swizzled)
//     aliases:  s_w half [0,9216) | s_h half [9216,27648) | s_tmp f32 [36992,71808)
//   [71808,90240)  s_o half [128][72] (swizzled)
//   [90240,92544)  s_m fp32 (576)
// ---------------------------------------------------------------------------
#define SMB_BYTES 92544

__global__ void __launch_bounds__(256,2) attn_ffn_kernel(
    const float* __restrict__ x,
    const float* __restrict__ ln1_g, const float* __restrict__ ln1_b,
    const float* __restrict__ ff1_b,
    const float* __restrict__ ff2_b,
    const float* __restrict__ ln2_g, const float* __restrict__ ln2_b,
    const float* __restrict__ bn_g, const float* __restrict__ bn_b,
    const float* __restrict__ bn_mean, const float* __restrict__ bn_var,
    float* __restrict__ out)
{
    extern __shared__ char smc[];
    float*  s_halo = (float*)smc;               // [264][68]
    __half* s_w    = (__half*)smc;              // [64][72]
    __half* s_h    = (__half*)(smc + 9216);     // [128][72]
    float*  s_tmp  = (float*)(smc + 36992);     // [128][68]
    __half* s_o    = (__half*)(smc + 71808);    // [128][72]
    float*  s_m    = (float*)(smc + 90240);

    const int tid = threadIdx.x;
    const int b  = blockIdx.z;
    const int y0 = blockIdx.y * 2;
    const int c0 = blockIdx.x * 64;

    // ---- issue k-halo cp.async ----
    #pragma unroll
    for (int r = 0; r < 4; r++) {
        const int gy = y0 + r - 1;
        const bool rowok = (unsigned)gy < HDIM;
        const float* src = g_k + (((long)b*HDIM + gy)*WDIM + c0 - 1)*64;
        for (int idx = tid; idx < 1056; idx += 256) {
            int j = idx >> 4, c4 = idx & 15;
            int gx = c0 + j - 1;
            int row = r*66 + j;
            int off = row*68 + SWZ(row, c4*4);
            int sz = (rowok && (unsigned)gx < WDIM) ? 16 : 0;
            CP16(sptr(s_halo + off), src + j*64 + c4*4, sz);
        }
    }
    CP_COMMIT;

    if (tid < 64) {
        s_m[tid]        = ln1_g[tid];
        s_m[64 + tid]   = ln1_b[tid];
        s_m[128 + tid]  = ln2_g[tid];
        s_m[192 + tid]  = ln2_b[tid];
        s_m[384 + tid]  = ff2_b[tid];
        float sc = bn_g[tid] * rsqrtf(bn_var[tid] + 1e-3f);
        s_m[448 + tid]  = sc;
        s_m[512 + tid]  = bn_b[tid] - bn_mean[tid]*sc;
    } else if (tid < 192) {
        s_m[256 + (tid - 64)] = ff1_b[tid - 64];
    }

    const int p  = tid >> 2;
    const int hd = tid & 3;
    const int base0 = ((b*HDIM + y0)*WDIM + c0 + p)*64;
    const int base1 = base0 + WDIM*64;

    float q0[16], q1[16];
    #pragma unroll
    for (int i = 0; i < 4; i++) {
        *(float4*)&q0[4*i] = *(const float4*)(g_q + base0 + hd*16 + 4*i);
        *(float4*)&q1[4*i] = *(const float4*)(g_q + base1 + hd*16 + 4*i);
    }
    CP_WAIT0;
    __syncthreads();

    // ---- scores for both rows ----
    float s0[9], s1[9];
    #pragma unroll
    for (int r = 0; r < 4; r++) {
        #pragma unroll
        for (int dx = 0; dx < 3; dx++) {
            int row = r*66 + p + dx;
            const float* kp = &s_halo[row*68 + ((hd ^ (row & 3)) << 4)];
            float kk[16];
            #pragma unroll
            for (int i = 0; i < 4; i++) *(float4*)&kk[4*i] = *(const float4*)&kp[4*i];
            if (r < 3) {
                float s = 0.f;
                #pragma unroll
                for (int dd = 0; dd < 16; dd++) s = fmaf(q0[dd], kk[dd], s);
                s0[r*3 + dx] = s * 0.25f;
            }
            if (r > 0) {
                float s = 0.f;
                #pragma unroll
                for (int dd = 0; dd < 16; dd++) s = fmaf(q1[dd], kk[dd], s);
                s1[(r-1)*3 + dx] = s * 0.25f;
            }
        }
    }
    float mx0 = s0[0], mx1 = s1[0];
    #pragma unroll
    for (int o = 1; o < 9; o++) { mx0 = fmaxf(mx0, s0[o]); mx1 = fmaxf(mx1, s1[o]); }
    float sum0 = 0.f, sum1 = 0.f;
    #pragma unroll
    for (int o = 0; o < 9; o++) {
        s0[o] = __expf(s0[o] - mx0); sum0 += s0[o];
        s1[o] = __expf(s1[o] - mx1); sum1 += s1[o];
    }
    const float si0 = 1.f/sum0, si1 = 1.f/sum1;
    #pragma unroll
    for (int o = 0; o < 9; o++) { s0[o] *= si0; s1[o] *= si1; }

    __syncthreads();   // all k-halo reads done

    // ---- issue v-halo cp.async ----
    #pragma unroll
    for (int r = 0; r < 4; r++) {
        const int gy = y0 + r - 1;
        const bool rowok = (unsigned)gy < HDIM;
        const float* src = g_v + (((long)b*HDIM + gy)*WDIM + c0 - 1)*64;
        for (int idx = tid; idx < 1056; idx += 256) {
            int j = idx >> 4, c4 = idx & 15;
            int gx = c0 + j - 1;
            int row = r*66 + j;
            int off = row*68 + SWZ(row, c4*4);
            int sz = (rowok && (unsigned)gx < WDIM) ? 16 : 0;
            CP16(sptr(s_halo + off), src + j*64 + c4*4, sz);
        }
    }
    CP_COMMIT;

    float xr0[16], xr1[16];
    #pragma unroll
    for (int i = 0; i < 4; i++) {
        *(float4*)&xr0[4*i] = *(const float4*)(x + base0 + hd*16 + 4*i);
        *(float4*)&xr1[4*i] = *(const float4*)(x + base1 + hd*16 + 4*i);
    }
    CP_WAIT0;
    __syncthreads();

    // ---- weighted v sums ----
    float a0[16], a1[16];
    #pragma unroll
    for (int dd = 0; dd < 16; dd++) { a0[dd] = 0.f; a1[dd] = 0.f; }
    #pragma unroll
    for (int r = 0; r < 4; r++) {
        #pragma unroll
        for (int dx = 0; dx < 3; dx++) {
            int row = r*66 + p + dx;
            const float* vp = &s_halo[row*68 + ((hd ^ (row & 3)) << 4)];
            float vv[16];
            #pragma unroll
            for (int i = 0; i < 4; i++) *(float4*)&vv[4*i] = *(const float4*)&vp[4*i];
            if (r < 3) {
                const float w = s0[r*3 + dx];
                #pragma unroll
                for (int dd = 0; dd < 16; dd++) a0[dd] = fmaf(w, vv[dd], a0[dd]);
            }
            if (r > 0) {
                const float w = s1[(r-1)*3 + dx];
                #pragma unroll
                for (int dd = 0; dd < 16; dd++) a1[dd] = fmaf(w, vv[dd], a1[dd]);
            }
        }
    }

    // ---- LN1 (+residual); fp16 into swizzled s_o ----
    #pragma unroll
    for (int rr = 0; rr < 2; rr++) {
        float* av = rr ? a1 : a0;
        float* xv = rr ? xr1 : xr0;
        float m1 = 0.f, m2 = 0.f;
        #pragma unroll
        for (int dd = 0; dd < 16; dd++) {
            av[dd] += xv[dd];
            m1 += av[dd];
            m2 = fmaf(av[dd], av[dd], m2);
        }
        m1 += __shfl_xor_sync(0xffffffff, m1, 1);
        m2 += __shfl_xor_sync(0xffffffff, m2, 1);
        m1 += __shfl_xor_sync(0xffffffff, m1, 2);
        m2 += __shfl_xor_sync(0xffffffff, m2, 2);
        const float mean = m1 * (1.f/64.f);
        const float var  = m2 * (1.f/64.f) - mean*mean;
        const float rstd = rsqrtf(var + 1e-3f);
        int row = rr*64 + p;
        __half2* dst = (__half2*)&s_o[row*72 + ((hd ^ (row & 3)) << 4)];
        #pragma unroll
        for (int i = 0; i < 4; i++) {
            const int c = hd*16 + 4*i;
            float w0 = (av[4*i+0] - mean)*rstd*s_m[c+0] + s_m[64+c+0];
            float w1 = (av[4*i+1] - mean)*rstd*s_m[c+1] + s_m[64+c+1];
            float w2 = (av[4*i+2] - mean)*rstd*s_m[c+2] + s_m[64+c+2];
            float w3 = (av[4*i+3] - mean)*rstd*s_m[c+3] + s_m[64+c+3];
            dst[2*i]   = __floats2half2_rn(w0, w1);
            dst[2*i+1] = __floats2half2_rn(w2, w3);
        }
    }
    __syncthreads();   // halo dead; LN1 visible

    const int wid = tid >> 5, lane = tid & 31;
    const int gr = lane >> 2, tg = lane & 3;
    const int m0 = (wid >> 1) * 32;
    const int wn = wid & 1;
    const unsigned* soU = (const unsigned*)s_o;
    const unsigned* shU = (const unsigned*)s_h;
    const unsigned* swU = (const unsigned*)s_w;

    // ---- fused FFN: per half P: GEMM1 -> s_h -> GEMM2 accumulate ----
    float d2[8][4];
    #pragma unroll
    for (int j = 0; j < 8; j++)
        #pragma unroll
        for (int c = 0; c < 4; c++) d2[j][c] = 0.f;

    #pragma unroll
    for (int P = 0; P < 2; P++) {
        {   // stage ff1 half P (9216 B)
            const char* src = (const char*)g_ff1n + P*9216;
            unsigned base = sptr(s_w);
            for (int i = tid; i < 576; i += 256) CP16(base + i*16, src + i*16, 16);
            CP_COMMIT;
        }
        CP_WAIT0;
        __syncthreads();
        float d1[8][4];
        #pragma unroll
        for (int j = 0; j < 8; j++)
            #pragma unroll
            for (int c = 0; c < 4; c++) d1[j][c] = 0.f;
        #pragma unroll
        for (int k0 = 0; k0 < 64; k0 += 16) {
            const int kc = k0 >> 1;
            unsigned a[2][4];
            #pragma unroll
            for (int t = 0; t < 2; t++) {
                int mr = m0 + 16*t + gr;
                int sw = (mr & 3) << 3;
                int base = mr*36;
                a[t][0] = soU[base       + ((kc+tg)   ^ sw)];
                a[t][1] = soU[base + 288 + ((kc+tg)   ^ sw)];
                a[t][2] = soU[base       + ((kc+tg+4) ^ sw)];
                a[t][3] = soU[base + 288 + ((kc+tg+4) ^ sw)];
            }
            #pragma unroll
            for (int j = 0; j < 4; j++) {
                int nn = wn*32 + j*8;
                unsigned b0 = swU[(nn+gr)*36 + kc+tg];
                unsigned b1 = swU[(nn+gr)*36 + kc+tg+4];
                #pragma unroll
                for (int t = 0; t < 2; t++)
                    mma_f16(d1[t*4+j], a[t][0], a[t][1], a[t][2], a[t][3], b0, b1);
            }
        }
        __syncthreads();   // s_w(ff1) reads done
        {   // stage ff2 half P, overlaps h writes
            const char* src = (const char*)g_ff2n + P*9216;
            unsigned base = sptr(s_w);
            for (int i = tid; i < 576; i += 256) CP16(base + i*16, src + i*16, 16);
            CP_COMMIT;
        }
        // write h half into swizzled s_h (fp16)
        #pragma unroll
        for (int t = 0; t < 2; t++) {
            #pragma unroll
            for (int j = 0; j < 4; j++) {
                int nl = wn*32 + j*8 + 2*tg;
                int ng = P*64 + nl;
                int mr = m0 + 16*t + gr;
                float bb0 = s_m[256 + ng], bb1 = s_m[256 + ng + 1];
                int sw4 = (mr & 3) << 4;
                *(__half2*)&s_h[mr*72 + (nl ^ sw4)] = __floats2half2_rn(
                    fmaxf(d1[t*4+j][0] + bb0, 0.f), fmaxf(d1[t*4+j][1] + bb1, 0.f));
                *(__half2*)&s_h[(mr+8)*72 + (nl ^ sw4)] = __floats2half2_rn(
                    fmaxf(d1[t*4+j][2] + bb0, 0.f), fmaxf(d1[t*4+j][3] + bb1, 0.f));
            }
        }
        CP_WAIT0;
        __syncthreads();
        // GEMM2 partial: d2 += h_P @ ff2_P
        #pragma unroll
        for (int k0 = 0; k0 < 64; k0 += 16) {
            const int kc = k0 >> 1;
            unsigned a[2][4];
            #pragma unroll
            for (int t = 0; t < 2; t++) {
                int mr = m0 + 16*t + gr;
                int sw = (mr & 3) << 3;
                int base = mr*36;
                a[t][0] = shU[base       + ((kc+tg)   ^ sw)];
                a[t][1] = shU[base + 288 + ((kc+tg)   ^ sw)];
                a[t][2] = shU[base       + ((kc+tg+4) ^ sw)];
                a[t][3] = shU[base + 288 + ((kc+tg+4) ^ sw)];
            }
            #pragma unroll
            for (int j = 0; j < 4; j++) {
                int nn = wn*32 + j*8;
                unsigned b0 = swU[(nn+gr)*36 + kc+tg];
                unsigned b1 = swU[(nn+gr)*36 + kc+tg+4];
                #pragma unroll
                for (int t = 0; t < 2; t++)
                    mma_f16(d2[t*4+j], a[t][0], a[t][1], a[t][2], a[t][3], b0, b1);
            }
        }
        __syncthreads();
    }

    // ---- GEMM2 epilogue: s_tmp (fp32) = o + d2 + b2 ----
    #pragma unroll
    for (int t = 0; t < 2; t++) {
        #pragma unroll
        for (int j = 0; j < 4; j++) {
            int n = wn*32 + j*8 + 2*tg;
            int mr = m0 + 16*t + gr;
            int sw4 = (mr & 3) << 4;
            float bb0 = s_m[384 + n], bb1 = s_m[384 + n + 1];
            float2 o0 = __half22float2(*(__half2*)&s_o[mr*72 + (n ^ sw4)]);
            float2 o1 = __half22float2(*(__half2*)&s_o[(mr+8)*72 + (n ^ sw4)]);
            *(float2*)&s_tmp[mr*68 + (n ^ sw4)] =
                make_float2(o0.x + d2[t*4+j][0] + bb0, o0.y + d2[t*4+j][1] + bb1);
            *(float2*)&s_tmp[(mr+8)*68 + (n ^ sw4)] =
                make_float2(o1.x + d2[t*4+j][2] + bb0, o1.y + d2[t*4+j][3] + bb1);
        }
    }
    __syncthreads();

    // stage fuse weights (s_w free; doesn't overlap s_tmp) — overlaps LN2
    {
        const char* src = (const char*)g_wfusen;
        unsigned base = sptr(s_w);
        for (int i = tid; i < 576; i += 256) CP16(base + i*16, src + i*16, 16);
        CP_COMMIT;
    }

    // ---- LN2: read s_tmp fp32, write fp16 s_o ----
    #pragma unroll
    for (int rr = 0; rr < 2; rr++) {
        int row = rr*64 + p;
        const float* rp = &s_tmp[row*68 + ((hd ^ (row & 3)) << 4)];
        float v2[16], m1 = 0.f, m2 = 0.f;
        #pragma unroll
        for (int i = 0; i < 4; i++) {
            float4 t4 = *(const float4*)&rp[4*i];
            v2[4*i+0] = t4.x; v2[4*i+1] = t4.y; v2[4*i+2] = t4.z; v2[4*i+3] = t4.w;
        }
        #pragma unroll
        for (int dd = 0; dd < 16; dd++) { m1 += v2[dd]; m2 = fmaf(v2[dd], v2[dd], m2); }
        m1 += __shfl_xor_sync(0xffffffff, m1, 1);
        m2 += __shfl_xor_sync(0xffffffff, m2, 1);
        m1 += __shfl_xor_sync(0xffffffff, m1, 2);
        m2 += __shfl_xor_sync(0xffffffff, m2, 2);
        const float mean = m1 * (1.f/64.f);
        const float var  = m2 * (1.f/64.f) - mean*mean;
        const float rstd = rsqrtf(var + 1e-3f);
        __half2* op = (__half2*)&s_o[row*72 + ((hd ^ (row & 3)) << 4)];
        #pragma unroll
        for (int i = 0; i < 4; i++) {
            const int c = hd*16 + 4*i;
            float w0 = (v2[4*i+0] - mean)*rstd*s_m[128+c+0] + s_m[192+c+0];
            float w1 = (v2[4*i+1] - mean)*rstd*s_m[128+c+1] + s_m[192+c+1];
            float w2 = (v2[4*i+2] - mean)*rstd*s_m[128+c+2] + s_m[192+c+2];
            float w3 = (v2[4*i+3] - mean)*rstd*s_m[128+c+3] + s_m[192+c+3];
            op[2*i]   = __floats2half2_rn(w0, w1);
            op[2*i+1] = __floats2half2_rn(w2, w3);
        }
    }
    CP_WAIT0;
    __syncthreads();

    // ---- GEMM3: fuse conv + BN + relu, direct global store ----
    {
        float d3[8][4];
        #pragma unroll
        for (int j = 0; j < 8; j++)
            #pragma unroll
            for (int c = 0; c < 4; c++) d3[j][c] = 0.f;
        #pragma unroll
        for (int k0 = 0; k0 < 64; k0 += 16) {
            const int kc = k0 >> 1;
            unsigned a[2][4];
            #pragma unroll
            for (int t = 0; t < 2; t++) {
                int mr = m0 + 16*t + gr;
                int sw = (mr & 3) << 3;
                int base = mr*36;
                a[t][0] = soU[base       + ((kc+tg)   ^ sw)];
                a[t][1] = soU[base + 288 + ((kc+tg)   ^ sw)];
                a[t][2] = soU[base       + ((kc+tg+4) ^ sw)];
                a[t][3] = soU[base + 288 + ((kc+tg+4) ^ sw)];
            }
            #pragma unroll
            for (int j = 0; j < 4; j++) {
                int nn = wn*32 + j*8;
                unsigned b0 = swU[(nn+gr)*36 + kc+tg];
                unsigned b1 = swU[(nn+gr)*36 + kc+tg+4];
                #pragma unroll
                for (int t = 0; t < 2; t++)
                    mma_f16(d3[t*4+j], a[t][0], a[t][1], a[t][2], a[t][3], b0, b1);
            }
        }
        #pragma unroll
        for (int t = 0; t < 2; t++) {
            #pragma unroll
            for (int j = 0; j < 4; j++) {
                int n = wn*32 + j*8 + 2*tg;
                int mr = m0 + 16*t + gr;
                int ry = mr >> 6, mx = mr & 63;
                float sc0 = s_m[448 + n], sc1 = s_m[448 + n + 1];
                float sh0 = s_m[512 + n], sh1 = s_m[512 + n + 1];
                float* ob0 = out + ((b*HDIM + y0 + ry)*WDIM + c0 + mx)*64;
                float* ob1 = out + ((b*HDIM + y0 + ry)*WDIM + c0 + mx + 8)*64;
                *(float2*)&ob0[n] = make_float2(
                    fmaxf(d3[t*4+j][0]*sc0 + sh0, 0.f), fmaxf(d3[t*4+j][1]*sc1 + sh1, 0.f));
                *(float2*)&ob1[n] = make_float2(
                    fmaxf(d3[t*4+j][2]*sc0 + sh0, 0.f), fmaxf(d3[t*4+j][3]*sc1 + sh1, 0.f));
            }
        }
    }
}

extern "C" void kernel_launch(void* const* d_in, const int* in_sizes, int n_in,
                              void* d_out, int out_size)
{
    const float* x      = (const float*)d_in[0];
    const float* wq     = (const float*)d_in[1];
    const float* wk     = (const float*)d_in[2];
    const float* wv     = (const float*)d_in[3];
    const float* ln1_g  = (const float*)d_in[4];
    const float* ln1_b  = (const float*)d_in[5];
    const float* ff1_w  = (const float*)d_in[6];
    const float* ff1_b  = (const float*)d_in[7];
    const float* ff2_w  = (const float*)d_in[8];
    const float* ff2_b  = (const float*)d_in[9];
    const float* ln2_g  = (const float*)d_in[10];
    const float* ln2_b  = (const float*)d_in[11];
    const float* w_fuse = (const float*)d_in[12];
    const float* bn_g   = (const float*)d_in[13];
    const float* bn_b   = (const float*)d_in[14];
    const float* bn_mean= (const float*)d_in[15];
    const float* bn_var = (const float*)d_in[16];
    float* out = (float*)d_out;

    const int SMEM_A = 46080;
    const int SMEM_B = SMB_BYTES;   // 92544
    cudaFuncSetAttribute(qkv_kernel, cudaFuncAttributeMaxDynamicSharedMemorySize, SMEM_A);
    cudaFuncSetAttribute(attn_ffn_kernel, cudaFuncAttributeMaxDynamicSharedMemorySize, SMEM_B);

    cvt_weights_kernel<<<144, 256>>>(wq, wk, wv, ff1_w, ff2_w, w_fuse);
    qkv_kernel<<<NPIX/128, 512, SMEM_A>>>(x);

    dim3 grid(WDIM/64, HDIM/2, BATCH);
    attn_ffn_kernel<<<grid, 256, SMEM_B>>>(
        x, ln1_g, ln1_b, ff1_b, ff2_b,
        ln2_g, ln2_b, bn_g, bn_b, bn_mean, bn_var, out);
}

// round 9
// speedup vs baseline: 3.0020x; 1.2723x over previous
#include <cuda_runtime.h>
#include <cuda_fp16.h>

#define BATCH 4
#define HDIM 384
#define WDIM 384
#define NPIX (BATCH*HDIM*WDIM)

// fp16 q/k/v scratch (halved HBM traffic)
__device__ __half g_q[NPIX*64];
__device__ __half g_k[NPIX*64];
__device__ __half g_v[NPIX*64];
// Pre-converted fp16 weights, B-operand layout [n][k] padded to 72
__device__ __half g_wqkv_h[192*72];
__device__ __half g_ff1n[128*72];
__device__ __half g_ff2n[2*64*72];
__device__ __half g_wfusen[64*72];

__device__ __forceinline__ void mma_f16(float* d,
    unsigned a0, unsigned a1, unsigned a2, unsigned a3,
    unsigned b0, unsigned b1)
{
    asm volatile("mma.sync.aligned.m16n8k16.row.col.f32.f16.f16.f32 "
        "{%0,%1,%2,%3}, {%4,%5,%6,%7}, {%8,%9}, {%0,%1,%2,%3};"
        : "+f"(d[0]), "+f"(d[1]), "+f"(d[2]), "+f"(d[3])
        : "r"(a0), "r"(a1), "r"(a2), "r"(a3), "r"(b0), "r"(b1));
}

__device__ __forceinline__ unsigned sptr(const void* p) {
    return (unsigned)__cvta_generic_to_shared((void*)p);
}
#define CP16(dst, src, sz) \
    asm volatile("cp.async.cg.shared.global [%0], [%1], 16, %2;" \
                 :: "r"(dst), "l"(src), "r"(sz))
#define CP_COMMIT asm volatile("cp.async.commit_group;" ::: "memory")
#define CP_WAIT0  asm volatile("cp.async.wait_group 0;"  ::: "memory")

// ---------------------------------------------------------------------------
// One-time weight prep
// ---------------------------------------------------------------------------
__global__ void __launch_bounds__(256) cvt_weights_kernel(
    const float* __restrict__ wq, const float* __restrict__ wk,
    const float* __restrict__ wv, const float* __restrict__ ff1_w,
    const float* __restrict__ ff2_w, const float* __restrict__ w_fuse)
{
    int i = blockIdx.x*256 + threadIdx.x;
    if (i < 13824) {
        int n = i / 72, k = i % 72;
        float v = 0.f;
        if (k < 64) {
            if (n < 64)       v = wq[k*64 + n];
            else if (n < 128) v = wk[k*64 + n - 64];
            else              v = wv[k*64 + n - 128];
        }
        g_wqkv_h[i] = __float2half_rn(v);
        return;
    }
    i -= 13824;
    if (i < 9216) {
        int n = i / 72, k = i % 72;
        g_ff1n[i] = __float2half_rn(k < 64 ? ff1_w[k*128 + n] : 0.f);
        return;
    }
    i -= 9216;
    if (i < 9216) {
        int P = i / 4608, r = i % 4608, n = r / 72, k = r % 72;
        g_ff2n[i] = __float2half_rn(k < 64 ? ff2_w[(P*64 + k)*64 + n] : 0.f);
        return;
    }
    i -= 9216;
    if (i < 4608) {
        int n = i / 72, k = i % 72;
        g_wfusen[i] = __float2half_rn(k < 64 ? w_fuse[k*64 + n] : 0.f);
    }
}

// ---------------------------------------------------------------------------
// Kernel A: qkv = x @ [wq|wk|wv], fp16 mma, fp16 output. 128 px, 512 thr.
// ---------------------------------------------------------------------------
__global__ void __launch_bounds__(512,1) qkv_kernel(const float* __restrict__ x)
{
    extern __shared__ char smc[];
    __half* ws = (__half*)smc;              // 27648 B
    __half* xs = (__half*)(smc + 27648);    // 18432 B
    const int tid = threadIdx.x;

    {
        const char* src = (const char*)g_wqkv_h;
        unsigned base = sptr(ws);
        for (int i = tid; i < 1728; i += 512) CP16(base + i*16, src + i*16, 16);
        CP_COMMIT;
    }
    const int pix0 = blockIdx.x * 128;
    const float4* xg = (const float4*)(x + pix0*64);
    for (int i = tid; i < 2048; i += 512) {
        int m = i >> 4, c4 = i & 15;
        float4 v = xg[i];
        int col = (4*c4) ^ ((m & 3) << 4);
        __half2* d = (__half2*)&xs[m*72 + col];
        d[0] = __floats2half2_rn(v.x, v.y);
        d[1] = __floats2half2_rn(v.z, v.w);
    }
    CP_WAIT0;
    __syncthreads();

    const int wid = tid >> 5, lane = tid & 31;
    const int gr = lane >> 2, tg = lane & 3;
    const int m0 = (wid >> 2) * 32;
    const int n0 = (wid & 3) * 48;
    const unsigned* xsU = (const unsigned*)xs;
    const unsigned* wsU = (const unsigned*)ws;

    float d[12][4];
    #pragma unroll
    for (int j = 0; j < 12; j++)
        #pragma unroll
        for (int c = 0; c < 4; c++) d[j][c] = 0.f;

    #pragma unroll
    for (int k0 = 0; k0 < 64; k0 += 16) {
        const int kc = k0 >> 1;
        unsigned a[2][4];
        #pragma unroll
        for (int t = 0; t < 2; t++) {
            int mr = m0 + 16*t + gr;
            int sw = (mr & 3) << 3;
            int base = mr*36;
            a[t][0] = xsU[base       + ((kc+tg)   ^ sw)];
            a[t][1] = xsU[base + 288 + ((kc+tg)   ^ sw)];
            a[t][2] = xsU[base       + ((kc+tg+4) ^ sw)];
            a[t][3] = xsU[base + 288 + ((kc+tg+4) ^ sw)];
        }
        #pragma unroll
        for (int j = 0; j < 6; j++) {
            int nn = n0 + j*8;
            unsigned b0 = wsU[(nn+gr)*36 + kc+tg];
            unsigned b1 = wsU[(nn+gr)*36 + kc+tg+4];
            #pragma unroll
            for (int t = 0; t < 2; t++)
                mma_f16(d[t*6+j], a[t][0], a[t][1], a[t][2], a[t][3], b0, b1);
        }
    }

    #pragma unroll
    for (int t = 0; t < 2; t++) {
        #pragma unroll
        for (int j = 0; j < 6; j++) {
            int n = n0 + j*8 + 2*tg;
            __half* dst; int nn;
            if (n < 64)       { dst = g_q; nn = n; }
            else if (n < 128) { dst = g_k; nn = n - 64; }
            else              { dst = g_v; nn = n - 128; }
            int m = pix0 + m0 + 16*t + gr;
            *(__half2*)&dst[m*64 + nn]     = __floats2half2_rn(d[t*6+j][0], d[t*6+j][1]);
            *(__half2*)&dst[(m+8)*64 + nn] = __floats2half2_rn(d[t*6+j][2], d[t*6+j][3]);
        }
    }
}

// ---------------------------------------------------------------------------
// Kernel B: fp16 halo attention (fp32 math) + fp16-MMA FFN/fuse.
// 128 px/block, 256 threads, 3 blocks/SM.
// smem bytes:
//   [0,44032)  region1: halo half [264][72]=38016 (swizzled)
//     aliases: s_w half [0,9216) | s_h half [9216,27648) | s_tmp f32 [9216,44032)
//   [44032,62464) s_o half [128][72] (swizzled)
//   [62464,64768) s_m fp32 (576)
// ---------------------------------------------------------------------------
#define SMB_BYTES 64768

__global__ void __launch_bounds__(256,3) attn_ffn_kernel(
    const float* __restrict__ x,
    const float* __restrict__ ln1_g, const float* __restrict__ ln1_b,
    const float* __restrict__ ff1_b,
    const float* __restrict__ ff2_b,
    const float* __restrict__ ln2_g, const float* __restrict__ ln2_b,
    const float* __restrict__ bn_g, const float* __restrict__ bn_b,
    const float* __restrict__ bn_mean, const float* __restrict__ bn_var,
    float* __restrict__ out)
{
    extern __shared__ char smc[];
    __half* s_halo = (__half*)smc;              // [264][72]
    __half* s_w    = (__half*)smc;              // [64][72]
    __half* s_h    = (__half*)(smc + 9216);     // [128][72]
    float*  s_tmp  = (float*)(smc + 9216);      // [128][68] (aliases s_h, used after)
    __half* s_o    = (__half*)(smc + 44032);    // [128][72]
    float*  s_m    = (float*)(smc + 62464);

    const int tid = threadIdx.x;
    const int b  = blockIdx.z;
    const int y0 = blockIdx.y * 2;
    const int c0 = blockIdx.x * 64;

    // ---- issue k-halo cp.async (fp16, swizzled) ----
    #pragma unroll
    for (int r = 0; r < 4; r++) {
        const int gy = y0 + r - 1;
        const bool rowok = (unsigned)gy < HDIM;
        const __half* src = g_k + (((long)b*HDIM + gy)*WDIM + c0 - 1)*64;
        for (int idx = tid; idx < 528; idx += 256) {
            int j = idx >> 3, c8 = idx & 7;
            int gx = c0 + j - 1;
            int row = r*66 + j;
            int off = row*72 + ((c8*8) ^ ((row & 3) << 4));
            int sz = (rowok && (unsigned)gx < WDIM) ? 16 : 0;
            CP16(sptr(s_halo + off), src + j*64 + c8*8, sz);
        }
    }
    CP_COMMIT;

    if (tid < 64) {
        s_m[tid]        = ln1_g[tid];
        s_m[64 + tid]   = ln1_b[tid];
        s_m[128 + tid]  = ln2_g[tid];
        s_m[192 + tid]  = ln2_b[tid];
        s_m[384 + tid]  = ff2_b[tid];
        float sc = bn_g[tid] * rsqrtf(bn_var[tid] + 1e-3f);
        s_m[448 + tid]  = sc;
        s_m[512 + tid]  = bn_b[tid] - bn_mean[tid]*sc;
    } else if (tid < 192) {
        s_m[256 + (tid - 64)] = ff1_b[tid - 64];
    }

    const int p  = tid >> 2;
    const int hd = tid & 3;
    const long base0 = (((long)b*HDIM + y0)*WDIM + c0 + p)*64;
    const long base1 = base0 + WDIM*64;

    float q0[16], q1[16];
    {
        union { uint4 u[2]; __half2 h[8]; } bq;
        bq.u[0] = *(const uint4*)(g_q + base0 + hd*16);
        bq.u[1] = *(const uint4*)(g_q + base0 + hd*16 + 8);
        #pragma unroll
        for (int i = 0; i < 8; i++) { float2 f = __half22float2(bq.h[i]); q0[2*i] = f.x; q0[2*i+1] = f.y; }
        bq.u[0] = *(const uint4*)(g_q + base1 + hd*16);
        bq.u[1] = *(const uint4*)(g_q + base1 + hd*16 + 8);
        #pragma unroll
        for (int i = 0; i < 8; i++) { float2 f = __half22float2(bq.h[i]); q1[2*i] = f.x; q1[2*i+1] = f.y; }
    }
    CP_WAIT0;
    __syncthreads();

    // ---- scores for both rows ----
    float s0[9], s1[9];
    #pragma unroll
    for (int r = 0; r < 4; r++) {
        #pragma unroll
        for (int dx = 0; dx < 3; dx++) {
            int row = r*66 + p + dx;
            const __half* kp = &s_halo[row*72 + ((hd ^ (row & 3)) << 4)];
            union { uint4 u[2]; __half2 h[8]; } bk;
            bk.u[0] = *(const uint4*)kp;
            bk.u[1] = *(const uint4*)(kp + 8);
            float kk[16];
            #pragma unroll
            for (int i = 0; i < 8; i++) { float2 f = __half22float2(bk.h[i]); kk[2*i] = f.x; kk[2*i+1] = f.y; }
            if (r < 3) {
                float s = 0.f;
                #pragma unroll
                for (int dd = 0; dd < 16; dd++) s = fmaf(q0[dd], kk[dd], s);
                s0[r*3 + dx] = s * 0.25f;
            }
            if (r > 0) {
                float s = 0.f;
                #pragma unroll
                for (int dd = 0; dd < 16; dd++) s = fmaf(q1[dd], kk[dd], s);
                s1[(r-1)*3 + dx] = s * 0.25f;
            }
        }
    }
    float mx0 = s0[0], mx1 = s1[0];
    #pragma unroll
    for (int o = 1; o < 9; o++) { mx0 = fmaxf(mx0, s0[o]); mx1 = fmaxf(mx1, s1[o]); }
    float sum0 = 0.f, sum1 = 0.f;
    #pragma unroll
    for (int o = 0; o < 9; o++) {
        s0[o] = __expf(s0[o] - mx0); sum0 += s0[o];
        s1[o] = __expf(s1[o] - mx1); sum1 += s1[o];
    }
    const float si0 = 1.f/sum0, si1 = 1.f/sum1;
    #pragma unroll
    for (int o = 0; o < 9; o++) { s0[o] *= si0; s1[o] *= si1; }

    __syncthreads();   // k-halo reads done

    // ---- issue v-halo cp.async ----
    #pragma unroll
    for (int r = 0; r < 4; r++) {
        const int gy = y0 + r - 1;
        const bool rowok = (unsigned)gy < HDIM;
        const __half* src = g_v + (((long)b*HDIM + gy)*WDIM + c0 - 1)*64;
        for (int idx = tid; idx < 528; idx += 256) {
            int j = idx >> 3, c8 = idx & 7;
            int gx = c0 + j - 1;
            int row = r*66 + j;
            int off = row*72 + ((c8*8) ^ ((row & 3) << 4));
            int sz = (rowok && (unsigned)gx < WDIM) ? 16 : 0;
            CP16(sptr(s_halo + off), src + j*64 + c8*8, sz);
        }
    }
    CP_COMMIT;

    float xr0[16], xr1[16];
    #pragma unroll
    for (int i = 0; i < 4; i++) {
        *(float4*)&xr0[4*i] = *(const float4*)(x + base0 + hd*16 + 4*i);
        *(float4*)&xr1[4*i] = *(const float4*)(x + base1 + hd*16 + 4*i);
    }
    CP_WAIT0;
    __syncthreads();

    // ---- weighted v sums ----
    float a0[16], a1[16];
    #pragma unroll
    for (int dd = 0; dd < 16; dd++) { a0[dd] = 0.f; a1[dd] = 0.f; }
    #pragma unroll
    for (int r = 0; r < 4; r++) {
        #pragma unroll
        for (int dx = 0; dx < 3; dx++) {
            int row = r*66 + p + dx;
            const __half* vp = &s_halo[row*72 + ((hd ^ (row & 3)) << 4)];
            union { uint4 u[2]; __half2 h[8]; } bv;
            bv.u[0] = *(const uint4*)vp;
            bv.u[1] = *(const uint4*)(vp + 8);
            float vv[16];
            #pragma unroll
            for (int i = 0; i < 8; i++) { float2 f = __half22float2(bv.h[i]); vv[2*i] = f.x; vv[2*i+1] = f.y; }
            if (r < 3) {
                const float w = s0[r*3 + dx];
                #pragma unroll
                for (int dd = 0; dd < 16; dd++) a0[dd] = fmaf(w, vv[dd], a0[dd]);
            }
            if (r > 0) {
                const float w = s1[(r-1)*3 + dx];
                #pragma unroll
                for (int dd = 0; dd < 16; dd++) a1[dd] = fmaf(w, vv[dd], a1[dd]);
            }
        }
    }

    // ---- LN1 (+residual); fp16 into swizzled s_o ----
    #pragma unroll
    for (int rr = 0; rr < 2; rr++) {
        float* av = rr ? a1 : a0;
        float* xv = rr ? xr1 : xr0;
        float m1 = 0.f, m2 = 0.f;
        #pragma unroll
        for (int dd = 0; dd < 16; dd++) {
            av[dd] += xv[dd];
            m1 += av[dd];
            m2 = fmaf(av[dd], av[dd], m2);
        }
        m1 += __shfl_xor_sync(0xffffffff, m1, 1);
        m2 += __shfl_xor_sync(0xffffffff, m2, 1);
        m1 += __shfl_xor_sync(0xffffffff, m1, 2);
        m2 += __shfl_xor_sync(0xffffffff, m2, 2);
        const float mean = m1 * (1.f/64.f);
        const float var  = m2 * (1.f/64.f) - mean*mean;
        const float rstd = rsqrtf(var + 1e-3f);
        int row = rr*64 + p;
        __half2* dst = (__half2*)&s_o[row*72 + ((hd ^ (row & 3)) << 4)];
        #pragma unroll
        for (int i = 0; i < 4; i++) {
            const int c = hd*16 + 4*i;
            float w0 = (av[4*i+0] - mean)*rstd*s_m[c+0] + s_m[64+c+0];
            float w1 = (av[4*i+1] - mean)*rstd*s_m[c+1] + s_m[64+c+1];
            float w2 = (av[4*i+2] - mean)*rstd*s_m[c+2] + s_m[64+c+2];
            float w3 = (av[4*i+3] - mean)*rstd*s_m[c+3] + s_m[64+c+3];
            dst[2*i]   = __floats2half2_rn(w0, w1);
            dst[2*i+1] = __floats2half2_rn(w2, w3);
        }
    }
    __syncthreads();   // halo dead; LN1 visible

    const int wid = tid >> 5, lane = tid & 31;
    const int gr = lane >> 2, tg = lane & 3;
    const int m0 = (wid >> 1) * 32;
    const int wn = wid & 1;
    const unsigned* soU = (const unsigned*)s_o;
    const unsigned* shU = (const unsigned*)s_h;
    const unsigned* swU = (const unsigned*)s_w;

    // ---- fused FFN: per half P: GEMM1 -> s_h -> GEMM2 accumulate ----
    float d2[8][4];
    #pragma unroll
    for (int j = 0; j < 8; j++)
        #pragma unroll
        for (int c = 0; c < 4; c++) d2[j][c] = 0.f;

    #pragma unroll
    for (int P = 0; P < 2; P++) {
        {
            const char* src = (const char*)g_ff1n + P*9216;
            unsigned base = sptr(s_w);
            for (int i = tid; i < 576; i += 256) CP16(base + i*16, src + i*16, 16);
            CP_COMMIT;
        }
        CP_WAIT0;
        __syncthreads();
        float d1[8][4];
        #pragma unroll
        for (int j = 0; j < 8; j++)
            #pragma unroll
            for (int c = 0; c < 4; c++) d1[j][c] = 0.f;
        #pragma unroll
        for (int k0 = 0; k0 < 64; k0 += 16) {
            const int kc = k0 >> 1;
            unsigned a[2][4];
            #pragma unroll
            for (int t = 0; t < 2; t++) {
                int mr = m0 + 16*t + gr;
                int sw = (mr & 3) << 3;
                int base = mr*36;
                a[t][0] = soU[base       + ((kc+tg)   ^ sw)];
                a[t][1] = soU[base + 288 + ((kc+tg)   ^ sw)];
                a[t][2] = soU[base       + ((kc+tg+4) ^ sw)];
                a[t][3] = soU[base + 288 + ((kc+tg+4) ^ sw)];
            }
            #pragma unroll
            for (int j = 0; j < 4; j++) {
                int nn = wn*32 + j*8;
                unsigned b0 = swU[(nn+gr)*36 + kc+tg];
                unsigned b1 = swU[(nn+gr)*36 + kc+tg+4];
                #pragma unroll
                for (int t = 0; t < 2; t++)
                    mma_f16(d1[t*4+j], a[t][0], a[t][1], a[t][2], a[t][3], b0, b1);
            }
        }
        __syncthreads();
        {
            const char* src = (const char*)g_ff2n + P*9216;
            unsigned base = sptr(s_w);
            for (int i = tid; i < 576; i += 256) CP16(base + i*16, src + i*16, 16);
            CP_COMMIT;
        }
        #pragma unroll
        for (int t = 0; t < 2; t++) {
            #pragma unroll
            for (int j = 0; j < 4; j++) {
                int nl = wn*32 + j*8 + 2*tg;
                int ng = P*64 + nl;
                int mr = m0 + 16*t + gr;
                float bb0 = s_m[256 + ng], bb1 = s_m[256 + ng + 1];
                int sw4 = (mr & 3) << 4;
                *(__half2*)&s_h[mr*72 + (nl ^ sw4)] = __floats2half2_rn(
                    fmaxf(d1[t*4+j][0] + bb0, 0.f), fmaxf(d1[t*4+j][1] + bb1, 0.f));
                *(__half2*)&s_h[(mr+8)*72 + (nl ^ sw4)] = __floats2half2_rn(
                    fmaxf(d1[t*4+j][2] + bb0, 0.f), fmaxf(d1[t*4+j][3] + bb1, 0.f));
            }
        }
        CP_WAIT0;
        __syncthreads();
        #pragma unroll
        for (int k0 = 0; k0 < 64; k0 += 16) {
            const int kc = k0 >> 1;
            unsigned a[2][4];
            #pragma unroll
            for (int t = 0; t < 2; t++) {
                int mr = m0 + 16*t + gr;
                int sw = (mr & 3) << 3;
                int base = mr*36;
                a[t][0] = shU[base       + ((kc+tg)   ^ sw)];
                a[t][1] = shU[base + 288 + ((kc+tg)   ^ sw)];
                a[t][2] = shU[base       + ((kc+tg+4) ^ sw)];
                a[t][3] = shU[base + 288 + ((kc+tg+4) ^ sw)];
            }
            #pragma unroll
            for (int j = 0; j < 4; j++) {
                int nn = wn*32 + j*8;
                unsigned b0 = swU[(nn+gr)*36 + kc+tg];
                unsigned b1 = swU[(nn+gr)*36 + kc+tg+4];
                #pragma unroll
                for (int t = 0; t < 2; t++)
                    mma_f16(d2[t*4+j], a[t][0], a[t][1], a[t][2], a[t][3], b0, b1);
            }
        }
        __syncthreads();
    }

    // ---- GEMM2 epilogue: s_tmp (fp32) = o + d2 + b2 (s_h dead) ----
    #pragma unroll
    for (int t = 0; t < 2; t++) {
        #pragma unroll
        for (int j = 0; j < 4; j++) {
            int n = wn*32 + j*8 + 2*tg;
            int mr = m0 + 16*t + gr;
            int sw4 = (mr & 3) << 4;
            float bb0 = s_m[384 + n], bb1 = s_m[384 + n + 1];
            float2 o0 = __half22float2(*(__half2*)&s_o[mr*72 + (n ^ sw4)]);
            float2 o1 = __half22float2(*(__half2*)&s_o[(mr+8)*72 + (n ^ sw4)]);
            *(float2*)&s_tmp[mr*68 + (n ^ sw4)] =
                make_float2(o0.x + d2[t*4+j][0] + bb0, o0.y + d2[t*4+j][1] + bb1);
            *(float2*)&s_tmp[(mr+8)*68 + (n ^ sw4)] =
                make_float2(o1.x + d2[t*4+j][2] + bb0, o1.y + d2[t*4+j][3] + bb1);
        }
    }
    __syncthreads();

    // stage fuse weights (s_w region distinct from s_tmp) — overlaps LN2
    {
        const char* src = (const char*)g_wfusen;
        unsigned base = sptr(s_w);
        for (int i = tid; i < 576; i += 256) CP16(base + i*16, src + i*16, 16);
        CP_COMMIT;
    }

    // ---- LN2: read s_tmp fp32, write fp16 s_o ----
    #pragma unroll
    for (int rr = 0; rr < 2; rr++) {
        int row = rr*64 + p;
        const float* rp = &s_tmp[row*68 + ((hd ^ (row & 3)) << 4)];
        float v2[16], m1 = 0.f, m2 = 0.f;
        #pragma unroll
        for (int i = 0; i < 4; i++) {
            float4 t4 = *(const float4*)&rp[4*i];
            v2[4*i+0] = t4.x; v2[4*i+1] = t4.y; v2[4*i+2] = t4.z; v2[4*i+3] = t4.w;
        }
        #pragma unroll
        for (int dd = 0; dd < 16; dd++) { m1 += v2[dd]; m2 = fmaf(v2[dd], v2[dd], m2); }
        m1 += __shfl_xor_sync(0xffffffff, m1, 1);
        m2 += __shfl_xor_sync(0xffffffff, m2, 1);
        m1 += __shfl_xor_sync(0xffffffff, m1, 2);
        m2 += __shfl_xor_sync(0xffffffff, m2, 2);
        const float mean = m1 * (1.f/64.f);
        const float var  = m2 * (1.f/64.f) - mean*mean;
        const float rstd = rsqrtf(var + 1e-3f);
        __half2* op = (__half2*)&s_o[row*72 + ((hd ^ (row & 3)) << 4)];
        #pragma unroll
        for (int i = 0; i < 4; i++) {
            const int c = hd*16 + 4*i;
            float w0 = (v2[4*i+0] - mean)*rstd*s_m[128+c+0] + s_m[192+c+0];
            float w1 = (v2[4*i+1] - mean)*rstd*s_m[128+c+1] + s_m[192+c+1];
            float w2 = (v2[4*i+2] - mean)*rstd*s_m[128+c+2] + s_m[192+c+2];
            float w3 = (v2[4*i+3] - mean)*rstd*s_m[128+c+3] + s_m[192+c+3];
            op[2*i]   = __floats2half2_rn(w0, w1);
            op[2*i+1] = __floats2half2_rn(w2, w3);
        }
    }
    CP_WAIT0;
    __syncthreads();

    // ---- GEMM3: fuse conv + BN + relu, direct global store ----
    {
        float d3[8][4];
        #pragma unroll
        for (int j = 0; j < 8; j++)
            #pragma unroll
            for (int c = 0; c < 4; c++) d3[j][c] = 0.f;
        #pragma unroll
        for (int k0 = 0; k0 < 64; k0 += 16) {
            const int kc = k0 >> 1;
            unsigned a[2][4];
            #pragma unroll
            for (int t = 0; t < 2; t++) {
                int mr = m0 + 16*t + gr;
                int sw = (mr & 3) << 3;
                int base = mr*36;
                a[t][0] = soU[base       + ((kc+tg)   ^ sw)];
                a[t][1] = soU[base + 288 + ((kc+tg)   ^ sw)];
                a[t][2] = soU[base       + ((kc+tg+4) ^ sw)];
                a[t][3] = soU[base + 288 + ((kc+tg+4) ^ sw)];
            }
            #pragma unroll
            for (int j = 0; j < 4; j++) {
                int nn = wn*32 + j*8;
                unsigned b0 = swU[(nn+gr)*36 + kc+tg];
                unsigned b1 = swU[(nn+gr)*36 + kc+tg+4];
                #pragma unroll
                for (int t = 0; t < 2; t++)
                    mma_f16(d3[t*4+j], a[t][0], a[t][1], a[t][2], a[t][3], b0, b1);
            }
        }
        #pragma unroll
        for (int t = 0; t < 2; t++) {
            #pragma unroll
            for (int j = 0; j < 4; j++) {
                int n = wn*32 + j*8 + 2*tg;
                int mr = m0 + 16*t + gr;
                int ry = mr >> 6, mx = mr & 63;
                float sc0 = s_m[448 + n], sc1 = s_m[448 + n + 1];
                float sh0 = s_m[512 + n], sh1 = s_m[512 + n + 1];
                float* ob0 = out + ((b*HDIM + y0 + ry)*WDIM + c0 + mx)*64;
                float* ob1 = out + ((b*HDIM + y0 + ry)*WDIM + c0 + mx + 8)*64;
                *(float2*)&ob0[n] = make_float2(
                    fmaxf(d3[t*4+j][0]*sc0 + sh0, 0.f), fmaxf(d3[t*4+j][1]*sc1 + sh1, 0.f));
                *(float2*)&ob1[n] = make_float2(
                    fmaxf(d3[t*4+j][2]*sc0 + sh0, 0.f), fmaxf(d3[t*4+j][3]*sc1 + sh1, 0.f));
            }
        }
    }
}

extern "C" void kernel_launch(void* const* d_in, const int* in_sizes, int n_in,
                              void* d_out, int out_size)
{
    const float* x      = (const float*)d_in[0];
    const float* wq     = (const float*)d_in[1];
    const float* wk     = (const float*)d_in[2];
    const float* wv     = (const float*)d_in[3];
    const float* ln1_g  = (const float*)d_in[4];
    const float* ln1_b  = (const float*)d_in[5];
    const float* ff1_w  = (const float*)d_in[6];
    const float* ff1_b  = (const float*)d_in[7];
    const float* ff2_w  = (const float*)d_in[8];
    const float* ff2_b  = (const float*)d_in[9];
    const float* ln2_g  = (const float*)d_in[10];
    const float* ln2_b  = (const float*)d_in[11];
    const float* w_fuse = (const float*)d_in[12];
    const float* bn_g   = (const float*)d_in[13];
    const float* bn_b   = (const float*)d_in[14];
    const float* bn_mean= (const float*)d_in[15];
    const float* bn_var = (const float*)d_in[16];
    float* out = (float*)d_out;

    const int SMEM_A = 46080;
    const int SMEM_B = SMB_BYTES;   // 64768
    cudaFuncSetAttribute(qkv_kernel, cudaFuncAttributeMaxDynamicSharedMemorySize, SMEM_A);
    cudaFuncSetAttribute(attn_ffn_kernel, cudaFuncAttributeMaxDynamicSharedMemorySize, SMEM_B);

    cvt_weights_kernel<<<144, 256>>>(wq, wk, wv, ff1_w, ff2_w, w_fuse);
    qkv_kernel<<<NPIX/128, 512, SMEM_A>>>(x);

    dim3 grid(WDIM/64, HDIM/2, BATCH);
    attn_ffn_kernel<<<grid, 256, SMEM_B>>>(
        x, ln1_g, ln1_b, ff1_b, ff2_b,
        ln2_g, ln2_b, bn_g, bn_b, bn_mean, bn_var, out);
}